// round 1
// baseline (speedup 1.0000x reference)
#include <cuda_runtime.h>
#include <math.h>

// Problem constants
#define BB 4
#define LL 4096
#define TT (BB*LL)        // 16384 tokens
#define DM 1024
#define HH 16
#define DH 64
#define MF 128            // d_kmap
#define TWO_M 256
#define KV_SPLIT 4

#define INV_SQRT_DH 0.125f
#define INV_SQRT_MF 0.08838834764831843f

// Scratch (global __device__ arrays: allocation-free per harness rules)
__device__ float g_q[TT*DM];
__device__ float g_k[TT*DM];
__device__ float g_v[TT*DM];
__device__ float g_att[TT*DM];
__device__ float g_kvp[(size_t)KV_SPLIT*BB*HH*TWO_M*DH];
__device__ float g_kv[(size_t)BB*HH*TWO_M*DH];

// ---------------------------------------------------------------------------
// GEMM: C[M,N] = A[M,K] * W[N,K]^T + bias[N]
// 128x128 block, BK=8, 256 threads, 8x8 microtile. All dims divide evenly.
// ---------------------------------------------------------------------------
__global__ __launch_bounds__(256) void gemm_nt_bias(
    const float* __restrict__ A, const float* __restrict__ W,
    const float* __restrict__ bias, float* __restrict__ C,
    int M, int N, int K)
{
    const int BM = 128, BN = 128, BK = 8;
    __shared__ float As[BK][BM];
    __shared__ float Bs[BK][BN];

    int bm = blockIdx.y * BM;
    int bn = blockIdx.x * BN;
    int tid = threadIdx.x;

    int lr = tid >> 1;            // 0..127
    int lc = (tid & 1) * 4;       // 0 or 4
    int tx = tid & 15;            // n-direction
    int ty = tid >> 4;            // m-direction

    const float* Ap = A + (size_t)(bm + lr) * K + lc;
    const float* Wp = W + (size_t)(bn + lr) * K + lc;

    float acc[8][8];
#pragma unroll
    for (int i = 0; i < 8; i++)
#pragma unroll
        for (int j = 0; j < 8; j++) acc[i][j] = 0.f;

    for (int k0 = 0; k0 < K; k0 += BK) {
        float4 av = *(const float4*)(Ap + k0);
        float4 wv = *(const float4*)(Wp + k0);
        As[lc + 0][lr] = av.x; As[lc + 1][lr] = av.y;
        As[lc + 2][lr] = av.z; As[lc + 3][lr] = av.w;
        Bs[lc + 0][lr] = wv.x; Bs[lc + 1][lr] = wv.y;
        Bs[lc + 2][lr] = wv.z; Bs[lc + 3][lr] = wv.w;
        __syncthreads();

#pragma unroll
        for (int kk = 0; kk < BK; kk++) {
            float a[8], b[8];
            *(float4*)(a)     = *(const float4*)&As[kk][ty * 8];
            *(float4*)(a + 4) = *(const float4*)&As[kk][ty * 8 + 4];
            *(float4*)(b)     = *(const float4*)&Bs[kk][tx * 8];
            *(float4*)(b + 4) = *(const float4*)&Bs[kk][tx * 8 + 4];
#pragma unroll
            for (int i = 0; i < 8; i++)
#pragma unroll
                for (int j = 0; j < 8; j++)
                    acc[i][j] += a[i] * b[j];
        }
        __syncthreads();
    }

    int col0 = bn + tx * 8;
    float bb[8];
#pragma unroll
    for (int j = 0; j < 8; j++) bb[j] = bias[col0 + j];

#pragma unroll
    for (int i = 0; i < 8; i++) {
        int row = bm + ty * 8 + i;
        float4 o0 = make_float4(acc[i][0] + bb[0], acc[i][1] + bb[1],
                                acc[i][2] + bb[2], acc[i][3] + bb[3]);
        float4 o1 = make_float4(acc[i][4] + bb[4], acc[i][5] + bb[5],
                                acc[i][6] + bb[6], acc[i][7] + bb[7]);
        *(float4*)(C + (size_t)row * N + col0)     = o0;
        *(float4*)(C + (size_t)row * N + col0 + 4) = o1;
    }
}

// ---------------------------------------------------------------------------
// kv partial: for one (split, h, b): acc[m][d] += k'[l][m] * v[l][d]
// 256 threads, thread owns feature row m (64-float accumulator).
// ---------------------------------------------------------------------------
__global__ __launch_bounds__(256) void kv_partial(
    const float* __restrict__ Kmat, const float* __restrict__ Vmat,
    const float* __restrict__ proj, float* __restrict__ kvp)
{
    const int CH = 32;
    const int LSPLIT = LL / KV_SPLIT;   // 1024

    __shared__ float projs[DH * MF];    // 32 KB
    __shared__ float ks[CH][DH];        // 8 KB
    __shared__ float vs[CH][DH];        // 8 KB

    int split = blockIdx.x;
    int h = blockIdx.y;
    int b = blockIdx.z;
    int tid = threadIdx.x;
    int tm = tid & 127;
    bool issin = tid >= 128;

    for (int i = tid; i < DH * MF; i += 256) projs[i] = proj[i];

    float acc[DH];
#pragma unroll
    for (int d = 0; d < DH; d++) acc[d] = 0.f;

    int l0 = split * LSPLIT;
    for (int lc = 0; lc < LSPLIT; lc += CH) {
        __syncthreads();
#pragma unroll
        for (int j = 0; j < 2; j++) {
            int idx = tid * 2 + j;          // 0..511
            int i = idx >> 4;               // token 0..31
            int d4 = (idx & 15) * 4;
            size_t t = (size_t)(b * LL + l0 + lc + i);
            *(float4*)&ks[i][d4] = *(const float4*)(Kmat + t * DM + h * DH + d4);
            *(float4*)&vs[i][d4] = *(const float4*)(Vmat + t * DM + h * DH + d4);
        }
        __syncthreads();

        for (int i = 0; i < CH; i++) {
            float p = 0.f;
#pragma unroll
            for (int d = 0; d < DH; d++)
                p += ks[i][d] * projs[d * MF + tm];
            p *= INV_SQRT_DH;
            float f = (issin ? sinf(p) : cosf(p)) * INV_SQRT_MF;
#pragma unroll
            for (int d = 0; d < DH; d += 4) {
                float4 vv = *(const float4*)&vs[i][d];
                acc[d + 0] += f * vv.x;
                acc[d + 1] += f * vv.y;
                acc[d + 2] += f * vv.z;
                acc[d + 3] += f * vv.w;
            }
        }
    }

    float* out = kvp + (((size_t)split * BB * HH + b * HH + h) * TWO_M + tid) * DH;
#pragma unroll
    for (int d = 0; d < DH; d += 4)
        *(float4*)&out[d] = make_float4(acc[d], acc[d + 1], acc[d + 2], acc[d + 3]);
}

// ---------------------------------------------------------------------------
// Reduce KV_SPLIT partial kv buffers
// ---------------------------------------------------------------------------
__global__ void kv_reduce(const float4* __restrict__ kvp, float4* __restrict__ kv)
{
    const int N4 = BB * HH * TWO_M * DH / 4;
    int i = blockIdx.x * blockDim.x + threadIdx.x;
    if (i >= N4) return;
    float4 s = kvp[i];
#pragma unroll
    for (int sp = 1; sp < KV_SPLIT; sp++) {
        float4 t = kvp[(size_t)sp * N4 + i];
        s.x += t.x; s.y += t.y; s.z += t.z; s.w += t.w;
    }
    kv[i] = s;
}

// ---------------------------------------------------------------------------
// attn out: out[l,d] = sum_m q'[l][m] * kv[m][d] for one (b,h), 64-token chunk
// SMEM: kvs[256][64], qs[256][68] (transposed q', padded), qin[64][64]
// ---------------------------------------------------------------------------
#define OCH 64
#define QS_STRIDE 68
#define SMEM_ATTN ((TWO_M*DH + TWO_M*QS_STRIDE + OCH*DH) * 4)

__global__ __launch_bounds__(256) void attn_out(
    const float* __restrict__ Q, const float* __restrict__ kv,
    const float* __restrict__ proj, float* __restrict__ out)
{
    extern __shared__ float sm[];
    float* kvs = sm;                      // 256*64
    float* qs  = sm + TWO_M * DH;         // 256*68 (row stride 68)
    float* qin = qs + TWO_M * QS_STRIDE;  // 64*64

    int chunk = blockIdx.x;
    int h = blockIdx.y;
    int b = blockIdx.z;
    int tid = threadIdx.x;
    int tm = tid & 127;
    bool issin = tid >= 128;

    // load kv[b,h] into shared
    const float* kvsrc = kv + ((size_t)(b * HH + h)) * TWO_M * DH;
    for (int i = tid * 4; i < TWO_M * DH; i += 256 * 4)
        *(float4*)&kvs[i] = *(const float4*)&kvsrc[i];

    // load 64 q tokens into shared
    int l0 = chunk * OCH;
#pragma unroll
    for (int j = 0; j < 4; j++) {
        int f4 = tid + j * 256;          // 0..1023
        int i = f4 >> 4;                 // token
        int d4 = (f4 & 15) * 4;
        size_t t = (size_t)(b * LL + l0 + i);
        *(float4*)&qin[i * DH + d4] = *(const float4*)(Q + t * DM + h * DH + d4);
    }

    // hoist this thread's proj column into registers
    float preg[DH];
#pragma unroll
    for (int d = 0; d < DH; d++) preg[d] = proj[d * MF + tm];

    __syncthreads();

    // phase 2: compute q' transposed into qs[m][i]
    for (int i = 0; i < OCH; i++) {
        float p = 0.f;
#pragma unroll
        for (int d = 0; d < DH; d += 4) {
            float4 qv = *(const float4*)&qin[i * DH + d];
            p += qv.x * preg[d] + qv.y * preg[d + 1]
               + qv.z * preg[d + 2] + qv.w * preg[d + 3];
        }
        p *= INV_SQRT_DH;
        qs[tid * QS_STRIDE + i] = (issin ? sinf(p) : cosf(p)) * INV_SQRT_MF;
    }
    __syncthreads();

    // phase 3: out[i][d] = sum_m qs[m][i] * kvs[m][d], 4x4 register tile
    int td = tid & 15;     // d group
    int ti = tid >> 4;     // token group
    float acc[4][4];
#pragma unroll
    for (int i = 0; i < 4; i++)
#pragma unroll
        for (int j = 0; j < 4; j++) acc[i][j] = 0.f;

    for (int m = 0; m < TWO_M; m++) {
        float4 a = *(const float4*)&qs[m * QS_STRIDE + ti * 4];
        float4 bv = *(const float4*)&kvs[m * DH + td * 4];
        acc[0][0] += a.x * bv.x; acc[0][1] += a.x * bv.y; acc[0][2] += a.x * bv.z; acc[0][3] += a.x * bv.w;
        acc[1][0] += a.y * bv.x; acc[1][1] += a.y * bv.y; acc[1][2] += a.y * bv.z; acc[1][3] += a.y * bv.w;
        acc[2][0] += a.z * bv.x; acc[2][1] += a.z * bv.y; acc[2][2] += a.z * bv.z; acc[2][3] += a.z * bv.w;
        acc[3][0] += a.w * bv.x; acc[3][1] += a.w * bv.y; acc[3][2] += a.w * bv.z; acc[3][3] += a.w * bv.w;
    }

#pragma unroll
    for (int ii = 0; ii < 4; ii++) {
        int token = l0 + ti * 4 + ii;
        float4 o = make_float4(acc[ii][0], acc[ii][1], acc[ii][2], acc[ii][3]);
        *(float4*)(out + ((size_t)(b * LL + token)) * DM + h * DH + td * 4) = o;
    }
}

// ---------------------------------------------------------------------------
// Launch
// ---------------------------------------------------------------------------
extern "C" void kernel_launch(void* const* d_in, const int* in_sizes, int n_in,
                              void* d_out, int out_size)
{
    const float* x    = (const float*)d_in[0];
    const float* proj = (const float*)d_in[1];
    const float* Wq   = (const float*)d_in[2];
    const float* bq   = (const float*)d_in[3];
    const float* Wk   = (const float*)d_in[4];
    const float* bk   = (const float*)d_in[5];
    const float* Wv   = (const float*)d_in[6];
    const float* bv   = (const float*)d_in[7];
    const float* Wo   = (const float*)d_in[8];
    const float* bo   = (const float*)d_in[9];
    float* out = (float*)d_out;

    float *q, *k, *v, *att, *kvp, *kvf;
    cudaGetSymbolAddress((void**)&q,   g_q);
    cudaGetSymbolAddress((void**)&k,   g_k);
    cudaGetSymbolAddress((void**)&v,   g_v);
    cudaGetSymbolAddress((void**)&att, g_att);
    cudaGetSymbolAddress((void**)&kvp, g_kvp);
    cudaGetSymbolAddress((void**)&kvf, g_kv);

    static bool attr_set = false;
    if (!attr_set) {
        cudaFuncSetAttribute(attn_out, cudaFuncAttributeMaxDynamicSharedMemorySize,
                             SMEM_ATTN);
        attr_set = true;
    }

    dim3 gemm_grid(DM / 128, TT / 128);   // (8, 128)
    gemm_nt_bias<<<gemm_grid, 256>>>(x, Wq, bq, q, TT, DM, DM);
    gemm_nt_bias<<<gemm_grid, 256>>>(x, Wk, bk, k, TT, DM, DM);
    gemm_nt_bias<<<gemm_grid, 256>>>(x, Wv, bv, v, TT, DM, DM);

    kv_partial<<<dim3(KV_SPLIT, HH, BB), 256>>>(k, v, proj, kvp);

    const int N4 = BB * HH * TWO_M * DH / 4;
    kv_reduce<<<(N4 + 255) / 256, 256>>>((const float4*)kvp, (float4*)kvf);

    attn_out<<<dim3(LL / OCH, HH, BB), 256, SMEM_ATTN>>>(q, kvf, proj, att);

    gemm_nt_bias<<<gemm_grid, 256>>>(att, Wo, bo, out, TT, DM, DM);
}

// round 2
// speedup vs baseline: 2.1726x; 2.1726x over previous
#include <cuda_runtime.h>
#include <math.h>
#include <stdint.h>

// Problem constants
#define BB 4
#define LL 4096
#define TT (BB*LL)        // 16384 tokens
#define DM 1024
#define HH 16
#define DH 64
#define MF 128            // d_kmap
#define TWO_M 256
#define KV_SPLIT 8

#define INV_SQRT_DH 0.125f
#define INV_SQRT_MF 0.08838834764831843f

// Scratch
__device__ float g_q[TT*DM];
__device__ float g_k[TT*DM];
__device__ float g_v[TT*DM];
__device__ float g_att[TT*DM];
__device__ float g_kvp[(size_t)KV_SPLIT*BB*HH*TWO_M*DH];
__device__ float g_kv[(size_t)BB*HH*TWO_M*DH];

// ---------------------------------------------------------------------------
// TF32 tensor-core GEMM: C[M,N] = A[M,K] * W[N,K]^T + bias[N]
// 128x128 block, BK=32, 256 threads (8 warps, 2x4), warp tile 64x32.
// mma.sync.m16n8k8 tf32, fp32 accumulate. SMEM stride 36 -> conflict-free.
// ---------------------------------------------------------------------------
#define BKC 32
#define ASTR 36

__device__ __forceinline__ float tf32r(float x) {
    uint32_t u;
    asm("cvt.rna.tf32.f32 %0, %1;" : "=r"(u) : "f"(x));
    return __uint_as_float(u);
}

__device__ __forceinline__ void mma_tf32(float* d, const uint32_t* a, const uint32_t* b) {
    asm volatile(
        "mma.sync.aligned.m16n8k8.row.col.f32.tf32.tf32.f32 "
        "{%0,%1,%2,%3}, {%4,%5,%6,%7}, {%8,%9}, {%0,%1,%2,%3};\n"
        : "+f"(d[0]), "+f"(d[1]), "+f"(d[2]), "+f"(d[3])
        : "r"(a[0]), "r"(a[1]), "r"(a[2]), "r"(a[3]), "r"(b[0]), "r"(b[1]));
}

__global__ __launch_bounds__(256) void gemm_tf32_nt_bias(
    const float* __restrict__ A, const float* __restrict__ W,
    const float* __restrict__ bias, float* __restrict__ C,
    int M, int N, int K)
{
    __shared__ float As[128 * ASTR];
    __shared__ float Ws[128 * ASTR];

    const int tid = threadIdx.x;
    const int bm = blockIdx.y * 128;
    const int bn = blockIdx.x * 128;
    const int warp = tid >> 5, lane = tid & 31;
    const int wm = (warp & 1) * 64;   // warp m offset in tile
    const int wn = (warp >> 1) * 32;  // warp n offset in tile
    const int g = lane >> 2, c = lane & 3;

    float d[4][4][4];
#pragma unroll
    for (int mt = 0; mt < 4; mt++)
#pragma unroll
        for (int nt = 0; nt < 4; nt++)
#pragma unroll
            for (int r = 0; r < 4; r++) d[mt][nt][r] = 0.f;

    float4 ra[4], rw[4];
    // preload chunk 0
#pragma unroll
    for (int j = 0; j < 4; j++) {
        int id = tid + j * 256;
        int row = id >> 3, kq = (id & 7) << 2;
        ra[j] = *(const float4*)(A + (size_t)(bm + row) * K + kq);
        rw[j] = *(const float4*)(W + (size_t)(bn + row) * K + kq);
    }

    for (int k0 = 0; k0 < K; k0 += BKC) {
        // stage current chunk into SMEM with tf32 rounding
#pragma unroll
        for (int j = 0; j < 4; j++) {
            int id = tid + j * 256;
            int row = id >> 3, kq = (id & 7) << 2;
            float4 av = ra[j], wv = rw[j];
            av.x = tf32r(av.x); av.y = tf32r(av.y); av.z = tf32r(av.z); av.w = tf32r(av.w);
            wv.x = tf32r(wv.x); wv.y = tf32r(wv.y); wv.z = tf32r(wv.z); wv.w = tf32r(wv.w);
            *(float4*)&As[row * ASTR + kq] = av;
            *(float4*)&Ws[row * ASTR + kq] = wv;
        }
        __syncthreads();

        // prefetch next chunk
        if (k0 + BKC < K) {
#pragma unroll
            for (int j = 0; j < 4; j++) {
                int id = tid + j * 256;
                int row = id >> 3, kq = (id & 7) << 2;
                ra[j] = *(const float4*)(A + (size_t)(bm + row) * K + k0 + BKC + kq);
                rw[j] = *(const float4*)(W + (size_t)(bn + row) * K + k0 + BKC + kq);
            }
        }

#pragma unroll
        for (int ks = 0; ks < 4; ks++) {
            const int kb = ks * 8;
            uint32_t a[4][4], b[4][2];
#pragma unroll
            for (int mt = 0; mt < 4; mt++) {
                const float* p = &As[(wm + mt * 16 + g) * ASTR + kb + c];
                a[mt][0] = __float_as_uint(p[0]);
                a[mt][1] = __float_as_uint(p[8 * ASTR]);
                a[mt][2] = __float_as_uint(p[4]);
                a[mt][3] = __float_as_uint(p[8 * ASTR + 4]);
            }
#pragma unroll
            for (int nt = 0; nt < 4; nt++) {
                const float* p = &Ws[(wn + nt * 8 + g) * ASTR + kb + c];
                b[nt][0] = __float_as_uint(p[0]);
                b[nt][1] = __float_as_uint(p[4]);
            }
#pragma unroll
            for (int mt = 0; mt < 4; mt++)
#pragma unroll
                for (int nt = 0; nt < 4; nt++)
                    mma_tf32(d[mt][nt], a[mt], b[nt]);
        }
        __syncthreads();
    }

    // epilogue: D layout c0:(g, 2c) c1:(g, 2c+1) c2:(g+8, 2c) c3:(g+8, 2c+1)
#pragma unroll
    for (int nt = 0; nt < 4; nt++) {
        int col = bn + wn + nt * 8 + 2 * c;
        float b0 = bias[col], b1 = bias[col + 1];
#pragma unroll
        for (int mt = 0; mt < 4; mt++) {
            int row = bm + wm + mt * 16 + g;
            float2 o0 = make_float2(d[mt][nt][0] + b0, d[mt][nt][1] + b1);
            float2 o1 = make_float2(d[mt][nt][2] + b0, d[mt][nt][3] + b1);
            *(float2*)(C + (size_t)row * N + col) = o0;
            *(float2*)(C + (size_t)(row + 8) * N + col) = o1;
        }
    }
}

// ---------------------------------------------------------------------------
// kv partial: for one (split, h, b): acc[m][d] += k'[l][m] * v[l][d]
// ---------------------------------------------------------------------------
__global__ __launch_bounds__(256) void kv_partial(
    const float* __restrict__ Kmat, const float* __restrict__ Vmat,
    const float* __restrict__ proj, float* __restrict__ kvp)
{
    const int CH = 32;
    const int LSPLIT = LL / KV_SPLIT;

    __shared__ float projs[DH * MF];
    __shared__ float ks[CH][DH];
    __shared__ float vs[CH][DH];

    int split = blockIdx.x;
    int h = blockIdx.y;
    int b = blockIdx.z;
    int tid = threadIdx.x;
    int tm = tid & 127;
    bool issin = tid >= 128;

    for (int i = tid; i < DH * MF; i += 256) projs[i] = proj[i];

    float acc[DH];
#pragma unroll
    for (int d = 0; d < DH; d++) acc[d] = 0.f;

    int l0 = split * LSPLIT;
    for (int lc = 0; lc < LSPLIT; lc += CH) {
        __syncthreads();
#pragma unroll
        for (int j = 0; j < 2; j++) {
            int idx = tid * 2 + j;
            int i = idx >> 4;
            int d4 = (idx & 15) * 4;
            size_t t = (size_t)(b * LL + l0 + lc + i);
            *(float4*)&ks[i][d4] = *(const float4*)(Kmat + t * DM + h * DH + d4);
            *(float4*)&vs[i][d4] = *(const float4*)(Vmat + t * DM + h * DH + d4);
        }
        __syncthreads();

        for (int i = 0; i < CH; i++) {
            float p = 0.f;
#pragma unroll
            for (int d = 0; d < DH; d++)
                p += ks[i][d] * projs[d * MF + tm];
            p *= INV_SQRT_DH;
            float f = (issin ? __sinf(p) : __cosf(p)) * INV_SQRT_MF;
#pragma unroll
            for (int d = 0; d < DH; d += 4) {
                float4 vv = *(const float4*)&vs[i][d];
                acc[d + 0] += f * vv.x;
                acc[d + 1] += f * vv.y;
                acc[d + 2] += f * vv.z;
                acc[d + 3] += f * vv.w;
            }
        }
    }

    float* out = kvp + (((size_t)split * BB * HH + b * HH + h) * TWO_M + tid) * DH;
#pragma unroll
    for (int d = 0; d < DH; d += 4)
        *(float4*)&out[d] = make_float4(acc[d], acc[d + 1], acc[d + 2], acc[d + 3]);
}

// ---------------------------------------------------------------------------
__global__ void kv_reduce(const float4* __restrict__ kvp, float4* __restrict__ kv)
{
    const int N4 = BB * HH * TWO_M * DH / 4;
    int i = blockIdx.x * blockDim.x + threadIdx.x;
    if (i >= N4) return;
    float4 s = kvp[i];
#pragma unroll
    for (int sp = 1; sp < KV_SPLIT; sp++) {
        float4 t = kvp[(size_t)sp * N4 + i];
        s.x += t.x; s.y += t.y; s.z += t.z; s.w += t.w;
    }
    kv[i] = s;
}

// ---------------------------------------------------------------------------
// attn out: out[l,d] = sum_m q'[l][m] * kv[m][d] for one (b,h), 64-token chunk
// ---------------------------------------------------------------------------
#define OCH 64
#define QS_STRIDE 68
#define SMEM_ATTN ((TWO_M*DH + TWO_M*QS_STRIDE + OCH*DH) * 4)

__global__ __launch_bounds__(256) void attn_out(
    const float* __restrict__ Q, const float* __restrict__ kv,
    const float* __restrict__ proj, float* __restrict__ out)
{
    extern __shared__ float sm[];
    float* kvs = sm;
    float* qs  = sm + TWO_M * DH;
    float* qin = qs + TWO_M * QS_STRIDE;

    int chunk = blockIdx.x;
    int h = blockIdx.y;
    int b = blockIdx.z;
    int tid = threadIdx.x;
    int tm = tid & 127;
    bool issin = tid >= 128;

    const float* kvsrc = kv + ((size_t)(b * HH + h)) * TWO_M * DH;
    for (int i = tid * 4; i < TWO_M * DH; i += 256 * 4)
        *(float4*)&kvs[i] = *(const float4*)&kvsrc[i];

    int l0 = chunk * OCH;
#pragma unroll
    for (int j = 0; j < 4; j++) {
        int f4 = tid + j * 256;
        int i = f4 >> 4;
        int d4 = (f4 & 15) * 4;
        size_t t = (size_t)(b * LL + l0 + i);
        *(float4*)&qin[i * DH + d4] = *(const float4*)(Q + t * DM + h * DH + d4);
    }

    float preg[DH];
#pragma unroll
    for (int d = 0; d < DH; d++) preg[d] = proj[d * MF + tm];

    __syncthreads();

    for (int i = 0; i < OCH; i++) {
        float p = 0.f;
#pragma unroll
        for (int d = 0; d < DH; d += 4) {
            float4 qv = *(const float4*)&qin[i * DH + d];
            p += qv.x * preg[d] + qv.y * preg[d + 1]
               + qv.z * preg[d + 2] + qv.w * preg[d + 3];
        }
        p *= INV_SQRT_DH;
        qs[tid * QS_STRIDE + i] = (issin ? __sinf(p) : __cosf(p)) * INV_SQRT_MF;
    }
    __syncthreads();

    int td = tid & 15;
    int ti = tid >> 4;
    float acc[4][4];
#pragma unroll
    for (int i = 0; i < 4; i++)
#pragma unroll
        for (int j = 0; j < 4; j++) acc[i][j] = 0.f;

    for (int m = 0; m < TWO_M; m++) {
        float4 a = *(const float4*)&qs[m * QS_STRIDE + ti * 4];
        float4 bv = *(const float4*)&kvs[m * DH + td * 4];
        acc[0][0] += a.x * bv.x; acc[0][1] += a.x * bv.y; acc[0][2] += a.x * bv.z; acc[0][3] += a.x * bv.w;
        acc[1][0] += a.y * bv.x; acc[1][1] += a.y * bv.y; acc[1][2] += a.y * bv.z; acc[1][3] += a.y * bv.w;
        acc[2][0] += a.z * bv.x; acc[2][1] += a.z * bv.y; acc[2][2] += a.z * bv.z; acc[2][3] += a.z * bv.w;
        acc[3][0] += a.w * bv.x; acc[3][1] += a.w * bv.y; acc[3][2] += a.w * bv.z; acc[3][3] += a.w * bv.w;
    }

#pragma unroll
    for (int ii = 0; ii < 4; ii++) {
        int token = l0 + ti * 4 + ii;
        float4 o = make_float4(acc[ii][0], acc[ii][1], acc[ii][2], acc[ii][3]);
        *(float4*)(out + ((size_t)(b * LL + token)) * DM + h * DH + td * 4) = o;
    }
}

// ---------------------------------------------------------------------------
extern "C" void kernel_launch(void* const* d_in, const int* in_sizes, int n_in,
                              void* d_out, int out_size)
{
    const float* x    = (const float*)d_in[0];
    const float* proj = (const float*)d_in[1];
    const float* Wq   = (const float*)d_in[2];
    const float* bq   = (const float*)d_in[3];
    const float* Wk   = (const float*)d_in[4];
    const float* bk   = (const float*)d_in[5];
    const float* Wv   = (const float*)d_in[6];
    const float* bv   = (const float*)d_in[7];
    const float* Wo   = (const float*)d_in[8];
    const float* bo   = (const float*)d_in[9];
    float* out = (float*)d_out;

    float *q, *k, *v, *att, *kvp, *kvf;
    cudaGetSymbolAddress((void**)&q,   g_q);
    cudaGetSymbolAddress((void**)&k,   g_k);
    cudaGetSymbolAddress((void**)&v,   g_v);
    cudaGetSymbolAddress((void**)&att, g_att);
    cudaGetSymbolAddress((void**)&kvp, g_kvp);
    cudaGetSymbolAddress((void**)&kvf, g_kv);

    static bool attr_set = false;
    if (!attr_set) {
        cudaFuncSetAttribute(attn_out, cudaFuncAttributeMaxDynamicSharedMemorySize,
                             SMEM_ATTN);
        attr_set = true;
    }

    dim3 gemm_grid(DM / 128, TT / 128);   // (8, 128)
    gemm_tf32_nt_bias<<<gemm_grid, 256>>>(x, Wq, bq, q, TT, DM, DM);
    gemm_tf32_nt_bias<<<gemm_grid, 256>>>(x, Wk, bk, k, TT, DM, DM);
    gemm_tf32_nt_bias<<<gemm_grid, 256>>>(x, Wv, bv, v, TT, DM, DM);

    kv_partial<<<dim3(KV_SPLIT, HH, BB), 256>>>(k, v, proj, kvp);

    const int N4 = BB * HH * TWO_M * DH / 4;
    kv_reduce<<<(N4 + 255) / 256, 256>>>((const float4*)kvp, (float4*)kvf);

    attn_out<<<dim3(LL / OCH, HH, BB), 256, SMEM_ATTN>>>(q, kvf, proj, att);

    gemm_tf32_nt_bias<<<gemm_grid, 256>>>(att, Wo, bo, out, TT, DM, DM);
}

// round 3
// speedup vs baseline: 3.7008x; 1.7034x over previous
#include <cuda_runtime.h>
#include <math.h>
#include <stdint.h>

#define BB 4
#define LL 4096
#define TT (BB*LL)
#define DM 1024
#define HH 16
#define DH 64
#define MF 128
#define TWO_M 256
#define KV_SPLIT 8
#define LSPLIT (LL/KV_SPLIT)   // 512

#define INV_SQRT_DH 0.125f
#define INV_SQRT_MF 0.08838834764831843f

__device__ float g_q[TT*DM];
__device__ float g_k[TT*DM];
__device__ float g_v[TT*DM];
__device__ float g_att[TT*DM];
__device__ float g_kvp[(size_t)KV_SPLIT*BB*HH*TWO_M*DH];
__device__ float g_kv[(size_t)BB*HH*TWO_M*DH];

__device__ __forceinline__ float tf32r(float x) {
    uint32_t u;
    asm("cvt.rna.tf32.f32 %0, %1;" : "=r"(u) : "f"(x));
    return __uint_as_float(u);
}

__device__ __forceinline__ void mma_tf32(float* d, const uint32_t* a, const uint32_t* b) {
    asm volatile(
        "mma.sync.aligned.m16n8k8.row.col.f32.tf32.tf32.f32 "
        "{%0,%1,%2,%3}, {%4,%5,%6,%7}, {%8,%9}, {%0,%1,%2,%3};\n"
        : "+f"(d[0]), "+f"(d[1]), "+f"(d[2]), "+f"(d[3])
        : "r"(a[0]), "r"(a[1]), "r"(a[2]), "r"(a[3]), "r"(b[0]), "r"(b[1]));
}

// ---------------------------------------------------------------------------
// TF32 GEMM: C[M,N] = A[M,K] * W[N,K]^T + bias (unchanged from R2)
// ---------------------------------------------------------------------------
#define BKC 32
#define ASTR 36

__global__ __launch_bounds__(256) void gemm_tf32_nt_bias(
    const float* __restrict__ A, const float* __restrict__ W,
    const float* __restrict__ bias, float* __restrict__ C,
    int M, int N, int K)
{
    __shared__ float As[128 * ASTR];
    __shared__ float Ws[128 * ASTR];

    const int tid = threadIdx.x;
    const int bm = blockIdx.y * 128;
    const int bn = blockIdx.x * 128;
    const int warp = tid >> 5, lane = tid & 31;
    const int wm = (warp & 1) * 64;
    const int wn = (warp >> 1) * 32;
    const int g = lane >> 2, c = lane & 3;

    float d[4][4][4];
#pragma unroll
    for (int mt = 0; mt < 4; mt++)
#pragma unroll
        for (int nt = 0; nt < 4; nt++)
#pragma unroll
            for (int r = 0; r < 4; r++) d[mt][nt][r] = 0.f;

    float4 ra[4], rw[4];
#pragma unroll
    for (int j = 0; j < 4; j++) {
        int id = tid + j * 256;
        int row = id >> 3, kq = (id & 7) << 2;
        ra[j] = *(const float4*)(A + (size_t)(bm + row) * K + kq);
        rw[j] = *(const float4*)(W + (size_t)(bn + row) * K + kq);
    }

    for (int k0 = 0; k0 < K; k0 += BKC) {
#pragma unroll
        for (int j = 0; j < 4; j++) {
            int id = tid + j * 256;
            int row = id >> 3, kq = (id & 7) << 2;
            float4 av = ra[j], wv = rw[j];
            av.x = tf32r(av.x); av.y = tf32r(av.y); av.z = tf32r(av.z); av.w = tf32r(av.w);
            wv.x = tf32r(wv.x); wv.y = tf32r(wv.y); wv.z = tf32r(wv.z); wv.w = tf32r(wv.w);
            *(float4*)&As[row * ASTR + kq] = av;
            *(float4*)&Ws[row * ASTR + kq] = wv;
        }
        __syncthreads();

        if (k0 + BKC < K) {
#pragma unroll
            for (int j = 0; j < 4; j++) {
                int id = tid + j * 256;
                int row = id >> 3, kq = (id & 7) << 2;
                ra[j] = *(const float4*)(A + (size_t)(bm + row) * K + k0 + BKC + kq);
                rw[j] = *(const float4*)(W + (size_t)(bn + row) * K + k0 + BKC + kq);
            }
        }

#pragma unroll
        for (int ks = 0; ks < 4; ks++) {
            const int kb = ks * 8;
            uint32_t a[4][4], b[4][2];
#pragma unroll
            for (int mt = 0; mt < 4; mt++) {
                const float* p = &As[(wm + mt * 16 + g) * ASTR + kb + c];
                a[mt][0] = __float_as_uint(p[0]);
                a[mt][1] = __float_as_uint(p[8 * ASTR]);
                a[mt][2] = __float_as_uint(p[4]);
                a[mt][3] = __float_as_uint(p[8 * ASTR + 4]);
            }
#pragma unroll
            for (int nt = 0; nt < 4; nt++) {
                const float* p = &Ws[(wn + nt * 8 + g) * ASTR + kb + c];
                b[nt][0] = __float_as_uint(p[0]);
                b[nt][1] = __float_as_uint(p[4]);
            }
#pragma unroll
            for (int mt = 0; mt < 4; mt++)
#pragma unroll
                for (int nt = 0; nt < 4; nt++)
                    mma_tf32(d[mt][nt], a[mt], b[nt]);
        }
        __syncthreads();
    }

#pragma unroll
    for (int nt = 0; nt < 4; nt++) {
        int col = bn + wn + nt * 8 + 2 * c;
        float b0 = bias[col], b1 = bias[col + 1];
#pragma unroll
        for (int mt = 0; mt < 4; mt++) {
            int row = bm + wm + mt * 16 + g;
            *(float2*)(C + (size_t)row * N + col) =
                make_float2(d[mt][nt][0] + b0, d[mt][nt][1] + b1);
            *(float2*)(C + (size_t)(row + 8) * N + col) =
                make_float2(d[mt][nt][2] + b0, d[mt][nt][3] + b1);
        }
    }
}

// ---------------------------------------------------------------------------
// feat_kv: per (split,h,b): kv[256,64] = sum_l k'(l)^T v(l) via tf32 MMA
// Step A: P[64tok,128m] = K @ projT  (K hi/lo split: 2 MMAs)
// features in registers -> k'T[256][68] SMEM
// Step B: kv += k'T[256,64tok] @ V  (V transposed in SMEM)
// ---------------------------------------------------------------------------
#define FSTR 68
#define FEAT_SMEM ((128*FSTR + 3*64*FSTR + 256*FSTR) * 4)   // 153 KB

__global__ __launch_bounds__(256) void feat_kv(
    const float* __restrict__ Kmat, const float* __restrict__ Vmat,
    const float* __restrict__ proj, float* __restrict__ kvp)
{
    extern __shared__ float sm[];
    float* projT = sm;                    // [128][68]
    float* ksh   = projT + 128 * FSTR;    // [64][68]
    float* ksl   = ksh   + 64 * FSTR;     // [64][68]
    float* vts   = ksl   + 64 * FSTR;     // [64 d][68 tok]
    float* kpt   = vts   + 64 * FSTR;     // [256 m'][68 tok]

    const int split = blockIdx.x, h = blockIdx.y, b = blockIdx.z;
    const int tid = threadIdx.x;
    const int warp = tid >> 5, lane = tid & 31;
    const int g = lane >> 2, c = lane & 3;

    // load projT[m][d] = proj[d][m], tf32-rounded
    for (int it = tid; it < 2048; it += 256) {
        int d = it >> 5;
        int m4 = (it & 31) * 4;
        float4 pv = *(const float4*)(proj + d * MF + m4);
        projT[(m4 + 0) * FSTR + d] = tf32r(pv.x);
        projT[(m4 + 1) * FSTR + d] = tf32r(pv.y);
        projT[(m4 + 2) * FSTR + d] = tf32r(pv.z);
        projT[(m4 + 3) * FSTR + d] = tf32r(pv.w);
    }

    float kvacc[4][4][4];
#pragma unroll
    for (int mi = 0; mi < 4; mi++)
#pragma unroll
        for (int nj = 0; nj < 4; nj++)
#pragma unroll
            for (int r = 0; r < 4; r++) kvacc[mi][nj][r] = 0.f;

    const int wtokA = (warp & 1) * 32, wmA = (warp >> 1) * 32;
    const int wmB = (warp & 3) * 64, wdB = (warp >> 2) * 32;
    const int l0 = split * LSPLIT;

    for (int ch = 0; ch < LSPLIT; ch += 64) {
        __syncthreads();
        // load K chunk (hi/lo split) + V chunk transposed
        for (int it = tid; it < 1024; it += 256) {
            int t = it >> 4;
            int d4 = (it & 15) * 4;
            size_t row = (size_t)(b * LL + l0 + ch + t) * DM + h * DH + d4;
            float4 kvv = *(const float4*)(Kmat + row);
            float hx, hy, hz, hw;
            hx = tf32r(kvv.x); hy = tf32r(kvv.y); hz = tf32r(kvv.z); hw = tf32r(kvv.w);
            *(float4*)&ksh[t * FSTR + d4] = make_float4(hx, hy, hz, hw);
            *(float4*)&ksl[t * FSTR + d4] = make_float4(
                tf32r(kvv.x - hx), tf32r(kvv.y - hy), tf32r(kvv.z - hz), tf32r(kvv.w - hw));
            float4 vv = *(const float4*)(Vmat + row);
            vts[(d4 + 0) * FSTR + t] = tf32r(vv.x);
            vts[(d4 + 1) * FSTR + t] = tf32r(vv.y);
            vts[(d4 + 2) * FSTR + t] = tf32r(vv.z);
            vts[(d4 + 3) * FSTR + t] = tf32r(vv.w);
        }
        __syncthreads();

        // Step A: P = K @ projT
        float pacc[2][4][4];
#pragma unroll
        for (int ti = 0; ti < 2; ti++)
#pragma unroll
            for (int nj = 0; nj < 4; nj++)
#pragma unroll
                for (int r = 0; r < 4; r++) pacc[ti][nj][r] = 0.f;

#pragma unroll
        for (int ks = 0; ks < 8; ks++) {
            const int kb = ks * 8;
            uint32_t ah[2][4], al[2][4], bf[4][2];
#pragma unroll
            for (int ti = 0; ti < 2; ti++) {
                const float* p = &ksh[(wtokA + ti * 16 + g) * FSTR + kb + c];
                ah[ti][0] = __float_as_uint(p[0]);
                ah[ti][1] = __float_as_uint(p[8 * FSTR]);
                ah[ti][2] = __float_as_uint(p[4]);
                ah[ti][3] = __float_as_uint(p[8 * FSTR + 4]);
                const float* q = &ksl[(wtokA + ti * 16 + g) * FSTR + kb + c];
                al[ti][0] = __float_as_uint(q[0]);
                al[ti][1] = __float_as_uint(q[8 * FSTR]);
                al[ti][2] = __float_as_uint(q[4]);
                al[ti][3] = __float_as_uint(q[8 * FSTR + 4]);
            }
#pragma unroll
            for (int nj = 0; nj < 4; nj++) {
                const float* p = &projT[(wmA + nj * 8 + g) * FSTR + kb + c];
                bf[nj][0] = __float_as_uint(p[0]);
                bf[nj][1] = __float_as_uint(p[4]);
            }
#pragma unroll
            for (int ti = 0; ti < 2; ti++)
#pragma unroll
                for (int nj = 0; nj < 4; nj++) {
                    mma_tf32(pacc[ti][nj], ah[ti], bf[nj]);
                    mma_tf32(pacc[ti][nj], al[ti], bf[nj]);
                }
        }

        // features -> kpt transposed [m'][tok]
#pragma unroll
        for (int ti = 0; ti < 2; ti++)
#pragma unroll
            for (int nj = 0; nj < 4; nj++) {
                int tok0 = wtokA + ti * 16 + g;
                int m0 = wmA + nj * 8 + 2 * c;
#pragma unroll
                for (int r = 0; r < 4; r++) {
                    int tok = tok0 + (r >> 1) * 8;
                    int m = m0 + (r & 1);
                    float p = pacc[ti][nj][r] * INV_SQRT_DH;
                    kpt[m * FSTR + tok] = tf32r(__cosf(p) * INV_SQRT_MF);
                    kpt[(m + 128) * FSTR + tok] = tf32r(__sinf(p) * INV_SQRT_MF);
                }
            }
        __syncthreads();

        // Step B: kv += k'T @ V
#pragma unroll
        for (int ks = 0; ks < 8; ks++) {
            const int kb = ks * 8;
            uint32_t af[4][4], bf2[4][2];
#pragma unroll
            for (int mi = 0; mi < 4; mi++) {
                const float* p = &kpt[(wmB + mi * 16 + g) * FSTR + kb + c];
                af[mi][0] = __float_as_uint(p[0]);
                af[mi][1] = __float_as_uint(p[8 * FSTR]);
                af[mi][2] = __float_as_uint(p[4]);
                af[mi][3] = __float_as_uint(p[8 * FSTR + 4]);
            }
#pragma unroll
            for (int nj = 0; nj < 4; nj++) {
                const float* p = &vts[(wdB + nj * 8 + g) * FSTR + kb + c];
                bf2[nj][0] = __float_as_uint(p[0]);
                bf2[nj][1] = __float_as_uint(p[4]);
            }
#pragma unroll
            for (int mi = 0; mi < 4; mi++)
#pragma unroll
                for (int nj = 0; nj < 4; nj++)
                    mma_tf32(kvacc[mi][nj], af[mi], bf2[nj]);
        }
    }

    float* outp = kvp + (((size_t)split * BB * HH + b * HH + h)) * TWO_M * DH;
#pragma unroll
    for (int mi = 0; mi < 4; mi++)
#pragma unroll
        for (int nj = 0; nj < 4; nj++) {
            int m = wmB + mi * 16 + g;
            int d = wdB + nj * 8 + 2 * c;
            *(float2*)(outp + m * DH + d) =
                make_float2(kvacc[mi][nj][0], kvacc[mi][nj][1]);
            *(float2*)(outp + (m + 8) * DH + d) =
                make_float2(kvacc[mi][nj][2], kvacc[mi][nj][3]);
        }
}

// ---------------------------------------------------------------------------
__global__ void kv_reduce(const float4* __restrict__ kvp, float4* __restrict__ kv)
{
    const int N4 = BB * HH * TWO_M * DH / 4;
    int i = blockIdx.x * blockDim.x + threadIdx.x;
    if (i >= N4) return;
    float4 s = kvp[i];
#pragma unroll
    for (int sp = 1; sp < KV_SPLIT; sp++) {
        float4 t = kvp[(size_t)sp * N4 + i];
        s.x += t.x; s.y += t.y; s.z += t.z; s.w += t.w;
    }
    kv[i] = s;
}

// ---------------------------------------------------------------------------
// attn: per (b,h): out[tok,64] = q'[tok,256] @ kv[256,64] via tf32 MMA
// 4 chunks of 64 tokens per block; projT/kvT loaded once.
// ---------------------------------------------------------------------------
#define ACH 4
#define QSTR 260
#define ATTN_SMEM ((128*FSTR + 2*64*FSTR + 2*64*QSTR) * 4)   // 198 KB

__global__ __launch_bounds__(256) void attn_mma(
    const float* __restrict__ Q, const float* __restrict__ kv,
    const float* __restrict__ proj, float* __restrict__ out)
{
    extern __shared__ float sm[];
    float* projT = sm;                    // [128][68]
    float* qsh   = projT + 128 * FSTR;    // [64][68]
    float* qsl   = qsh   + 64 * FSTR;     // [64][68]
    float* qps   = qsl   + 64 * FSTR;     // [64 tok][260]
    float* kvt   = qps   + 64 * QSTR;     // [64 d][260 m']

    const int h = blockIdx.y, b = blockIdx.z;
    const int tid = threadIdx.x;
    const int warp = tid >> 5, lane = tid & 31;
    const int g = lane >> 2, c = lane & 3;

    for (int it = tid; it < 2048; it += 256) {
        int d = it >> 5;
        int m4 = (it & 31) * 4;
        float4 pv = *(const float4*)(proj + d * MF + m4);
        projT[(m4 + 0) * FSTR + d] = tf32r(pv.x);
        projT[(m4 + 1) * FSTR + d] = tf32r(pv.y);
        projT[(m4 + 2) * FSTR + d] = tf32r(pv.z);
        projT[(m4 + 3) * FSTR + d] = tf32r(pv.w);
    }
    // kvT[d][m'] = kv[m'][d]
    const float* kvsrc = kv + ((size_t)(b * HH + h)) * TWO_M * DH;
    for (int it = tid; it < 4096; it += 256) {
        int m = it >> 4;
        int d4 = (it & 15) * 4;
        float4 v = *(const float4*)(kvsrc + m * DH + d4);
        kvt[(d4 + 0) * QSTR + m] = tf32r(v.x);
        kvt[(d4 + 1) * QSTR + m] = tf32r(v.y);
        kvt[(d4 + 2) * QSTR + m] = tf32r(v.z);
        kvt[(d4 + 3) * QSTR + m] = tf32r(v.w);
    }

    const int wtokA = (warp & 1) * 32, wmA = (warp >> 1) * 32;
    const int wtok3 = (warp & 1) * 32, wd3 = (warp >> 1) * 16;

    for (int cc = 0; cc < ACH; cc++) {
        const int l0 = (blockIdx.x * ACH + cc) * 64;
        __syncthreads();
        for (int it = tid; it < 1024; it += 256) {
            int t = it >> 4;
            int d4 = (it & 15) * 4;
            size_t row = (size_t)(b * LL + l0 + t) * DM + h * DH + d4;
            float4 qv = *(const float4*)(Q + row);
            float hx = tf32r(qv.x), hy = tf32r(qv.y), hz = tf32r(qv.z), hw = tf32r(qv.w);
            *(float4*)&qsh[t * FSTR + d4] = make_float4(hx, hy, hz, hw);
            *(float4*)&qsl[t * FSTR + d4] = make_float4(
                tf32r(qv.x - hx), tf32r(qv.y - hy), tf32r(qv.z - hz), tf32r(qv.w - hw));
        }
        __syncthreads();

        // Step A: P = Q @ projT
        float pacc[2][4][4];
#pragma unroll
        for (int ti = 0; ti < 2; ti++)
#pragma unroll
            for (int nj = 0; nj < 4; nj++)
#pragma unroll
                for (int r = 0; r < 4; r++) pacc[ti][nj][r] = 0.f;

#pragma unroll
        for (int ks = 0; ks < 8; ks++) {
            const int kb = ks * 8;
            uint32_t ah[2][4], al[2][4], bf[4][2];
#pragma unroll
            for (int ti = 0; ti < 2; ti++) {
                const float* p = &qsh[(wtokA + ti * 16 + g) * FSTR + kb + c];
                ah[ti][0] = __float_as_uint(p[0]);
                ah[ti][1] = __float_as_uint(p[8 * FSTR]);
                ah[ti][2] = __float_as_uint(p[4]);
                ah[ti][3] = __float_as_uint(p[8 * FSTR + 4]);
                const float* q2 = &qsl[(wtokA + ti * 16 + g) * FSTR + kb + c];
                al[ti][0] = __float_as_uint(q2[0]);
                al[ti][1] = __float_as_uint(q2[8 * FSTR]);
                al[ti][2] = __float_as_uint(q2[4]);
                al[ti][3] = __float_as_uint(q2[8 * FSTR + 4]);
            }
#pragma unroll
            for (int nj = 0; nj < 4; nj++) {
                const float* p = &projT[(wmA + nj * 8 + g) * FSTR + kb + c];
                bf[nj][0] = __float_as_uint(p[0]);
                bf[nj][1] = __float_as_uint(p[4]);
            }
#pragma unroll
            for (int ti = 0; ti < 2; ti++)
#pragma unroll
                for (int nj = 0; nj < 4; nj++) {
                    mma_tf32(pacc[ti][nj], ah[ti], bf[nj]);
                    mma_tf32(pacc[ti][nj], al[ti], bf[nj]);
                }
        }

        // q' row-major [tok][m'] (cos | sin)
#pragma unroll
        for (int ti = 0; ti < 2; ti++)
#pragma unroll
            for (int nj = 0; nj < 4; nj++) {
                int tok0 = wtokA + ti * 16 + g;
                int m0 = wmA + nj * 8 + 2 * c;
#pragma unroll
                for (int half = 0; half < 2; half++) {
                    int tok = tok0 + half * 8;
                    float p0 = pacc[ti][nj][half * 2 + 0] * INV_SQRT_DH;
                    float p1 = pacc[ti][nj][half * 2 + 1] * INV_SQRT_DH;
                    *(float2*)&qps[tok * QSTR + m0] = make_float2(
                        tf32r(__cosf(p0) * INV_SQRT_MF), tf32r(__cosf(p1) * INV_SQRT_MF));
                    *(float2*)&qps[tok * QSTR + m0 + 128] = make_float2(
                        tf32r(__sinf(p0) * INV_SQRT_MF), tf32r(__sinf(p1) * INV_SQRT_MF));
                }
            }
        __syncthreads();

        // Step B: out[64,64] = q'[64,256] @ kvT
        float oacc[2][2][4];
#pragma unroll
        for (int mi = 0; mi < 2; mi++)
#pragma unroll
            for (int nj = 0; nj < 2; nj++)
#pragma unroll
                for (int r = 0; r < 4; r++) oacc[mi][nj][r] = 0.f;

#pragma unroll
        for (int ks = 0; ks < 32; ks++) {
            const int kb = ks * 8;
            uint32_t af[2][4], bf2[2][2];
#pragma unroll
            for (int mi = 0; mi < 2; mi++) {
                const float* p = &qps[(wtok3 + mi * 16 + g) * QSTR + kb + c];
                af[mi][0] = __float_as_uint(p[0]);
                af[mi][1] = __float_as_uint(p[8 * QSTR]);
                af[mi][2] = __float_as_uint(p[4]);
                af[mi][3] = __float_as_uint(p[8 * QSTR + 4]);
            }
#pragma unroll
            for (int nj = 0; nj < 2; nj++) {
                const float* p = &kvt[(wd3 + nj * 8 + g) * QSTR + kb + c];
                bf2[nj][0] = __float_as_uint(p[0]);
                bf2[nj][1] = __float_as_uint(p[4]);
            }
#pragma unroll
            for (int mi = 0; mi < 2; mi++)
#pragma unroll
                for (int nj = 0; nj < 2; nj++)
                    mma_tf32(oacc[mi][nj], af[mi], bf2[nj]);
        }

#pragma unroll
        for (int mi = 0; mi < 2; mi++)
#pragma unroll
            for (int nj = 0; nj < 2; nj++) {
                int tok = l0 + wtok3 + mi * 16 + g;
                int col = h * DH + wd3 + nj * 8 + 2 * c;
                *(float2*)(out + (size_t)(b * LL + tok) * DM + col) =
                    make_float2(oacc[mi][nj][0], oacc[mi][nj][1]);
                *(float2*)(out + (size_t)(b * LL + tok + 8) * DM + col) =
                    make_float2(oacc[mi][nj][2], oacc[mi][nj][3]);
            }
    }
}

// ---------------------------------------------------------------------------
extern "C" void kernel_launch(void* const* d_in, const int* in_sizes, int n_in,
                              void* d_out, int out_size)
{
    const float* x    = (const float*)d_in[0];
    const float* proj = (const float*)d_in[1];
    const float* Wq   = (const float*)d_in[2];
    const float* bq   = (const float*)d_in[3];
    const float* Wk   = (const float*)d_in[4];
    const float* bk   = (const float*)d_in[5];
    const float* Wv   = (const float*)d_in[6];
    const float* bv   = (const float*)d_in[7];
    const float* Wo   = (const float*)d_in[8];
    const float* bo   = (const float*)d_in[9];
    float* out = (float*)d_out;

    float *q, *k, *v, *att, *kvp, *kvf;
    cudaGetSymbolAddress((void**)&q,   g_q);
    cudaGetSymbolAddress((void**)&k,   g_k);
    cudaGetSymbolAddress((void**)&v,   g_v);
    cudaGetSymbolAddress((void**)&att, g_att);
    cudaGetSymbolAddress((void**)&kvp, g_kvp);
    cudaGetSymbolAddress((void**)&kvf, g_kv);

    static bool attr_set = false;
    if (!attr_set) {
        cudaFuncSetAttribute(feat_kv, cudaFuncAttributeMaxDynamicSharedMemorySize, FEAT_SMEM);
        cudaFuncSetAttribute(attn_mma, cudaFuncAttributeMaxDynamicSharedMemorySize, ATTN_SMEM);
        attr_set = true;
    }

    dim3 gemm_grid(DM / 128, TT / 128);
    gemm_tf32_nt_bias<<<gemm_grid, 256>>>(x, Wq, bq, q, TT, DM, DM);
    gemm_tf32_nt_bias<<<gemm_grid, 256>>>(x, Wk, bk, k, TT, DM, DM);
    gemm_tf32_nt_bias<<<gemm_grid, 256>>>(x, Wv, bv, v, TT, DM, DM);

    feat_kv<<<dim3(KV_SPLIT, HH, BB), 256, FEAT_SMEM>>>(k, v, proj, kvp);

    const int N4 = BB * HH * TWO_M * DH / 4;
    kv_reduce<<<(N4 + 255) / 256, 256>>>((const float4*)kvp, (float4*)kvf);

    attn_mma<<<dim3(LL / (64 * ACH), HH, BB), 256, ATTN_SMEM>>>(q, kvf, proj, att);

    gemm_tf32_nt_bias<<<gemm_grid, 256>>>(att, Wo, bo, out, TT, DM, DM);
}

// round 4
// speedup vs baseline: 4.0662x; 1.0987x over previous
#include <cuda_runtime.h>
#include <math.h>
#include <stdint.h>

#define BB 4
#define LL 4096
#define TT (BB*LL)
#define DM 1024
#define HH 16
#define DH 64
#define MF 128
#define TWO_M 256
#define KV_SPLIT 16
#define LSPLIT (LL/KV_SPLIT)   // 256

#define INV_SQRT_DH 0.125f
#define INV_SQRT_MF 0.08838834764831843f

__device__ float g_q[TT*DM];
__device__ float g_k[TT*DM];
__device__ float g_v[TT*DM];
__device__ float g_att[TT*DM];
__device__ float g_xr[TT*DM];
__device__ float g_wr[4*DM*DM];
__device__ float g_kvp[(size_t)KV_SPLIT*BB*HH*TWO_M*DH];
__device__ float g_kv[(size_t)BB*HH*TWO_M*DH];

__device__ __forceinline__ float tf32r(float x) {
    uint32_t u;
    asm("cvt.rna.tf32.f32 %0, %1;" : "=r"(u) : "f"(x));
    return __uint_as_float(u);
}

__device__ __forceinline__ void mma_tf32(float* d, const uint32_t* a, const uint32_t* b) {
    asm volatile(
        "mma.sync.aligned.m16n8k8.row.col.f32.tf32.tf32.f32 "
        "{%0,%1,%2,%3}, {%4,%5,%6,%7}, {%8,%9}, {%0,%1,%2,%3};\n"
        : "+f"(d[0]), "+f"(d[1]), "+f"(d[2]), "+f"(d[3])
        : "r"(a[0]), "r"(a[1]), "r"(a[2]), "r"(a[3]), "r"(b[0]), "r"(b[1]));
}

// ---------------------------------------------------------------------------
// prep: round fp32 -> tf32 in place of a copy
// ---------------------------------------------------------------------------
__global__ void round_cp(const float4* __restrict__ src, float4* __restrict__ dst, int n4)
{
    int i = blockIdx.x * 256 + threadIdx.x;
    if (i < n4) {
        float4 v = src[i];
        v.x = tf32r(v.x); v.y = tf32r(v.y); v.z = tf32r(v.z); v.w = tf32r(v.w);
        dst[i] = v;
    }
}

// ---------------------------------------------------------------------------
// GEMM body: C[128,128 tile] = A[M,1024] * W[N,1024]^T + bias
// cp.async 3-stage pipeline, inputs pre-rounded to tf32. 256 threads.
// ---------------------------------------------------------------------------
#define GS 3
#define GSTR 36
#define GSTAGE (128*GSTR)          // 4608 floats
#define GSMEM (2*GS*GSTAGE*4)      // 110592 bytes

__device__ __forceinline__ void gemm_body(
    const float* __restrict__ A, const float* __restrict__ W,
    const float* __restrict__ bias, float* __restrict__ C)
{
    extern __shared__ float sg[];
    float* As = sg;
    float* Ws = sg + GS * GSTAGE;

    const int tid = threadIdx.x;
    const int bm = blockIdx.y * 128;
    const int bn = blockIdx.x * 128;
    const int warp = tid >> 5, lane = tid & 31;
    const int wm = (warp & 1) * 64;
    const int wn = (warp >> 1) * 32;
    const int g = lane >> 2, c = lane & 3;

    float d[4][4][4];
#pragma unroll
    for (int mt = 0; mt < 4; mt++)
#pragma unroll
        for (int nt = 0; nt < 4; nt++)
#pragma unroll
            for (int r = 0; r < 4; r++) d[mt][nt][r] = 0.f;

    auto issue = [&](int st, int k0) {
#pragma unroll
        for (int j = 0; j < 4; j++) {
            int id = tid + j * 256;
            int row = id >> 3, kq = (id & 7) * 4;
            uint32_t da = (uint32_t)__cvta_generic_to_shared(&As[st * GSTAGE + row * GSTR + kq]);
            uint32_t dw = (uint32_t)__cvta_generic_to_shared(&Ws[st * GSTAGE + row * GSTR + kq]);
            asm volatile("cp.async.cg.shared.global [%0], [%1], 16;\n"
                         :: "r"(da), "l"(A + (size_t)(bm + row) * DM + k0 + kq));
            asm volatile("cp.async.cg.shared.global [%0], [%1], 16;\n"
                         :: "r"(dw), "l"(W + (size_t)(bn + row) * DM + k0 + kq));
        }
    };

    issue(0, 0);  asm volatile("cp.async.commit_group;\n");
    issue(1, 32); asm volatile("cp.async.commit_group;\n");

    const int NIT = DM / 32;   // 32
    for (int i = 0; i < NIT; i++) {
        asm volatile("cp.async.wait_group 1;\n");
        __syncthreads();
        if (i + 2 < NIT) issue((i + 2) % GS, (i + 2) * 32);
        asm volatile("cp.async.commit_group;\n");

        const float* Ab = As + (i % GS) * GSTAGE;
        const float* Wb = Ws + (i % GS) * GSTAGE;
#pragma unroll
        for (int ks = 0; ks < 4; ks++) {
            const int kb = ks * 8;
            uint32_t a[4][4], b[4][2];
#pragma unroll
            for (int mt = 0; mt < 4; mt++) {
                const float* p = &Ab[(wm + mt * 16 + g) * GSTR + kb + c];
                a[mt][0] = __float_as_uint(p[0]);
                a[mt][1] = __float_as_uint(p[8 * GSTR]);
                a[mt][2] = __float_as_uint(p[4]);
                a[mt][3] = __float_as_uint(p[8 * GSTR + 4]);
            }
#pragma unroll
            for (int nt = 0; nt < 4; nt++) {
                const float* p = &Wb[(wn + nt * 8 + g) * GSTR + kb + c];
                b[nt][0] = __float_as_uint(p[0]);
                b[nt][1] = __float_as_uint(p[4]);
            }
#pragma unroll
            for (int mt = 0; mt < 4; mt++)
#pragma unroll
                for (int nt = 0; nt < 4; nt++)
                    mma_tf32(d[mt][nt], a[mt], b[nt]);
        }
    }

#pragma unroll
    for (int nt = 0; nt < 4; nt++) {
        int col = bn + wn + nt * 8 + 2 * c;
        float b0 = bias[col], b1 = bias[col + 1];
#pragma unroll
        for (int mt = 0; mt < 4; mt++) {
            int row = bm + wm + mt * 16 + g;
            *(float2*)(C + (size_t)row * DM + col) =
                make_float2(d[mt][nt][0] + b0, d[mt][nt][1] + b1);
            *(float2*)(C + (size_t)(row + 8) * DM + col) =
                make_float2(d[mt][nt][2] + b0, d[mt][nt][3] + b1);
        }
    }
}

__global__ __launch_bounds__(256, 2) void qkv_gemm(
    const float* __restrict__ A, const float* __restrict__ Wr,
    const float* __restrict__ bq, const float* __restrict__ bk, const float* __restrict__ bv,
    float* __restrict__ q, float* __restrict__ k, float* __restrict__ v)
{
    int z = blockIdx.z;
    const float* W = Wr + (size_t)z * DM * DM;
    const float* bias = (z == 0) ? bq : (z == 1) ? bk : bv;
    float* C = (z == 0) ? q : (z == 1) ? k : v;
    gemm_body(A, W, bias, C);
}

__global__ __launch_bounds__(256, 2) void gemm_one(
    const float* __restrict__ A, const float* __restrict__ W,
    const float* __restrict__ bias, float* __restrict__ C)
{
    gemm_body(A, W, bias, C);
}

// ---------------------------------------------------------------------------
// feat_kv: per (split,h,b): kv[256,64] = sum_l k'(l)^T v(l). 512 threads.
// ---------------------------------------------------------------------------
#define FSTR 68
#define FEAT_SMEM ((128*FSTR + 3*64*FSTR + 256*FSTR) * 4)

__global__ __launch_bounds__(512) void feat_kv(
    const float* __restrict__ Kmat, const float* __restrict__ Vmat,
    const float* __restrict__ proj, float* __restrict__ kvp)
{
    extern __shared__ float sm[];
    float* projT = sm;                    // [128][68]
    float* ksh   = projT + 128 * FSTR;    // [64][68]
    float* ksl   = ksh   + 64 * FSTR;     // [64][68]
    float* vts   = ksl   + 64 * FSTR;     // [64 d][68 tok]
    float* kpt   = vts   + 64 * FSTR;     // [256 m'][68 tok]

    const int split = blockIdx.x, h = blockIdx.y, b = blockIdx.z;
    const int tid = threadIdx.x;
    const int warp = tid >> 5, lane = tid & 31;
    const int g = lane >> 2, c = lane & 3;

    for (int it = tid; it < 2048; it += 512) {
        int d = it >> 5;
        int m4 = (it & 31) * 4;
        float4 pv = *(const float4*)(proj + d * MF + m4);
        projT[(m4 + 0) * FSTR + d] = tf32r(pv.x);
        projT[(m4 + 1) * FSTR + d] = tf32r(pv.y);
        projT[(m4 + 2) * FSTR + d] = tf32r(pv.z);
        projT[(m4 + 3) * FSTR + d] = tf32r(pv.w);
    }

    float kvacc[4][2][4];
#pragma unroll
    for (int mi = 0; mi < 4; mi++)
#pragma unroll
        for (int nj = 0; nj < 2; nj++)
#pragma unroll
            for (int r = 0; r < 4; r++) kvacc[mi][nj][r] = 0.f;

    const int wtokA = (warp & 3) * 16, wmA = (warp >> 2) * 32;
    const int mB0 = (warp & 3) * 64, dB0 = (warp >> 2) * 16;
    const int l0 = split * LSPLIT;

    for (int ch = 0; ch < LSPLIT; ch += 64) {
        __syncthreads();
        for (int it = tid; it < 1024; it += 512) {
            int t = it >> 4;
            int d4 = (it & 15) * 4;
            size_t row = (size_t)(b * LL + l0 + ch + t) * DM + h * DH + d4;
            float4 kvv = *(const float4*)(Kmat + row);
            float hx = tf32r(kvv.x), hy = tf32r(kvv.y), hz = tf32r(kvv.z), hw = tf32r(kvv.w);
            *(float4*)&ksh[t * FSTR + d4] = make_float4(hx, hy, hz, hw);
            *(float4*)&ksl[t * FSTR + d4] = make_float4(
                tf32r(kvv.x - hx), tf32r(kvv.y - hy), tf32r(kvv.z - hz), tf32r(kvv.w - hw));
            float4 vv = *(const float4*)(Vmat + row);
            vts[(d4 + 0) * FSTR + t] = tf32r(vv.x);
            vts[(d4 + 1) * FSTR + t] = tf32r(vv.y);
            vts[(d4 + 2) * FSTR + t] = tf32r(vv.z);
            vts[(d4 + 3) * FSTR + t] = tf32r(vv.w);
        }
        __syncthreads();

        // Step A: P[64,128] = K @ projT (hi/lo)
        float pacc[4][4];
#pragma unroll
        for (int nj = 0; nj < 4; nj++)
#pragma unroll
            for (int r = 0; r < 4; r++) pacc[nj][r] = 0.f;

#pragma unroll
        for (int ks = 0; ks < 8; ks++) {
            const int kb = ks * 8;
            uint32_t ah[4], al[4], bf[4][2];
            const float* ph = &ksh[(wtokA + g) * FSTR + kb + c];
            ah[0] = __float_as_uint(ph[0]);
            ah[1] = __float_as_uint(ph[8 * FSTR]);
            ah[2] = __float_as_uint(ph[4]);
            ah[3] = __float_as_uint(ph[8 * FSTR + 4]);
            const float* pl = &ksl[(wtokA + g) * FSTR + kb + c];
            al[0] = __float_as_uint(pl[0]);
            al[1] = __float_as_uint(pl[8 * FSTR]);
            al[2] = __float_as_uint(pl[4]);
            al[3] = __float_as_uint(pl[8 * FSTR + 4]);
#pragma unroll
            for (int nj = 0; nj < 4; nj++) {
                const float* p = &projT[(wmA + nj * 8 + g) * FSTR + kb + c];
                bf[nj][0] = __float_as_uint(p[0]);
                bf[nj][1] = __float_as_uint(p[4]);
            }
#pragma unroll
            for (int nj = 0; nj < 4; nj++) {
                mma_tf32(pacc[nj], ah, bf[nj]);
                mma_tf32(pacc[nj], al, bf[nj]);
            }
        }

#pragma unroll
        for (int nj = 0; nj < 4; nj++)
#pragma unroll
            for (int r = 0; r < 4; r++) {
                int tok = wtokA + g + (r >> 1) * 8;
                int m = wmA + nj * 8 + 2 * c + (r & 1);
                float p = pacc[nj][r] * INV_SQRT_DH;
                kpt[m * FSTR + tok] = tf32r(__cosf(p) * INV_SQRT_MF);
                kpt[(m + 128) * FSTR + tok] = tf32r(__sinf(p) * INV_SQRT_MF);
            }
        __syncthreads();

        // Step B: kv[256,64] += k'T @ V
#pragma unroll
        for (int ks = 0; ks < 8; ks++) {
            const int kb = ks * 8;
            uint32_t af[4][4], bf2[2][2];
#pragma unroll
            for (int mi = 0; mi < 4; mi++) {
                const float* p = &kpt[(mB0 + mi * 16 + g) * FSTR + kb + c];
                af[mi][0] = __float_as_uint(p[0]);
                af[mi][1] = __float_as_uint(p[8 * FSTR]);
                af[mi][2] = __float_as_uint(p[4]);
                af[mi][3] = __float_as_uint(p[8 * FSTR + 4]);
            }
#pragma unroll
            for (int nj = 0; nj < 2; nj++) {
                const float* p = &vts[(dB0 + nj * 8 + g) * FSTR + kb + c];
                bf2[nj][0] = __float_as_uint(p[0]);
                bf2[nj][1] = __float_as_uint(p[4]);
            }
#pragma unroll
            for (int mi = 0; mi < 4; mi++)
#pragma unroll
                for (int nj = 0; nj < 2; nj++)
                    mma_tf32(kvacc[mi][nj], af[mi], bf2[nj]);
        }
    }

    float* outp = kvp + ((size_t)split * BB * HH + b * HH + h) * TWO_M * DH;
#pragma unroll
    for (int mi = 0; mi < 4; mi++)
#pragma unroll
        for (int nj = 0; nj < 2; nj++) {
            int m = mB0 + mi * 16 + g;
            int d = dB0 + nj * 8 + 2 * c;
            *(float2*)(outp + m * DH + d) =
                make_float2(kvacc[mi][nj][0], kvacc[mi][nj][1]);
            *(float2*)(outp + (m + 8) * DH + d) =
                make_float2(kvacc[mi][nj][2], kvacc[mi][nj][3]);
        }
}

// ---------------------------------------------------------------------------
__global__ void kv_reduce(const float4* __restrict__ kvp, float4* __restrict__ kv)
{
    const int N4 = BB * HH * TWO_M * DH / 4;
    int i = blockIdx.x * blockDim.x + threadIdx.x;
    if (i >= N4) return;
    float4 s = kvp[i];
#pragma unroll
    for (int sp = 1; sp < KV_SPLIT; sp++) {
        float4 t = kvp[(size_t)sp * N4 + i];
        s.x += t.x; s.y += t.y; s.z += t.z; s.w += t.w;
    }
    kv[i] = s;
}

// ---------------------------------------------------------------------------
// attn: out[tok,64] = q'[tok,256] @ kv[256,64]. 512 threads, ACH chunks/block.
// Writes att pre-rounded to tf32 (feeds final GEMM directly).
// ---------------------------------------------------------------------------
#define ACH 4
#define QSTR 260
#define ATTN_SMEM ((128*FSTR + 2*64*FSTR + 2*64*QSTR) * 4)

__global__ __launch_bounds__(512) void attn_mma(
    const float* __restrict__ Q, const float* __restrict__ kv,
    const float* __restrict__ proj, float* __restrict__ out)
{
    extern __shared__ float sm[];
    float* projT = sm;                    // [128][68]
    float* qsh   = projT + 128 * FSTR;    // [64][68]
    float* qsl   = qsh   + 64 * FSTR;     // [64][68]
    float* qps   = qsl   + 64 * FSTR;     // [64 tok][260]
    float* kvt   = qps   + 64 * QSTR;     // [64 d][260 m']

    const int h = blockIdx.y, b = blockIdx.z;
    const int tid = threadIdx.x;
    const int warp = tid >> 5, lane = tid & 31;
    const int g = lane >> 2, c = lane & 3;

    for (int it = tid; it < 2048; it += 512) {
        int d = it >> 5;
        int m4 = (it & 31) * 4;
        float4 pv = *(const float4*)(proj + d * MF + m4);
        projT[(m4 + 0) * FSTR + d] = tf32r(pv.x);
        projT[(m4 + 1) * FSTR + d] = tf32r(pv.y);
        projT[(m4 + 2) * FSTR + d] = tf32r(pv.z);
        projT[(m4 + 3) * FSTR + d] = tf32r(pv.w);
    }
    const float* kvsrc = kv + ((size_t)(b * HH + h)) * TWO_M * DH;
    for (int it = tid; it < 4096; it += 512) {
        int m = it >> 4;
        int d4 = (it & 15) * 4;
        float4 v = *(const float4*)(kvsrc + m * DH + d4);
        kvt[(d4 + 0) * QSTR + m] = tf32r(v.x);
        kvt[(d4 + 1) * QSTR + m] = tf32r(v.y);
        kvt[(d4 + 2) * QSTR + m] = tf32r(v.z);
        kvt[(d4 + 3) * QSTR + m] = tf32r(v.w);
    }

    const int wtokA = (warp & 3) * 16, wmA = (warp >> 2) * 32;
    const int tokB = (warp & 3) * 16, dB = (warp >> 2) * 16;

    for (int cc = 0; cc < ACH; cc++) {
        const int l0 = (blockIdx.x * ACH + cc) * 64;
        __syncthreads();
        for (int it = tid; it < 1024; it += 512) {
            int t = it >> 4;
            int d4 = (it & 15) * 4;
            size_t row = (size_t)(b * LL + l0 + t) * DM + h * DH + d4;
            float4 qv = *(const float4*)(Q + row);
            float hx = tf32r(qv.x), hy = tf32r(qv.y), hz = tf32r(qv.z), hw = tf32r(qv.w);
            *(float4*)&qsh[t * FSTR + d4] = make_float4(hx, hy, hz, hw);
            *(float4*)&qsl[t * FSTR + d4] = make_float4(
                tf32r(qv.x - hx), tf32r(qv.y - hy), tf32r(qv.z - hz), tf32r(qv.w - hw));
        }
        __syncthreads();

        // Step A: P = Q @ projT (hi/lo)
        float pacc[4][4];
#pragma unroll
        for (int nj = 0; nj < 4; nj++)
#pragma unroll
            for (int r = 0; r < 4; r++) pacc[nj][r] = 0.f;

#pragma unroll
        for (int ks = 0; ks < 8; ks++) {
            const int kb = ks * 8;
            uint32_t ah[4], al[4], bf[4][2];
            const float* ph = &qsh[(wtokA + g) * FSTR + kb + c];
            ah[0] = __float_as_uint(ph[0]);
            ah[1] = __float_as_uint(ph[8 * FSTR]);
            ah[2] = __float_as_uint(ph[4]);
            ah[3] = __float_as_uint(ph[8 * FSTR + 4]);
            const float* pl = &qsl[(wtokA + g) * FSTR + kb + c];
            al[0] = __float_as_uint(pl[0]);
            al[1] = __float_as_uint(pl[8 * FSTR]);
            al[2] = __float_as_uint(pl[4]);
            al[3] = __float_as_uint(pl[8 * FSTR + 4]);
#pragma unroll
            for (int nj = 0; nj < 4; nj++) {
                const float* p = &projT[(wmA + nj * 8 + g) * FSTR + kb + c];
                bf[nj][0] = __float_as_uint(p[0]);
                bf[nj][1] = __float_as_uint(p[4]);
            }
#pragma unroll
            for (int nj = 0; nj < 4; nj++) {
                mma_tf32(pacc[nj], ah, bf[nj]);
                mma_tf32(pacc[nj], al, bf[nj]);
            }
        }

#pragma unroll
        for (int nj = 0; nj < 4; nj++)
#pragma unroll
            for (int half = 0; half < 2; half++) {
                int tok = wtokA + g + half * 8;
                int m0 = wmA + nj * 8 + 2 * c;
                float p0 = pacc[nj][half * 2 + 0] * INV_SQRT_DH;
                float p1 = pacc[nj][half * 2 + 1] * INV_SQRT_DH;
                *(float2*)&qps[tok * QSTR + m0] = make_float2(
                    tf32r(__cosf(p0) * INV_SQRT_MF), tf32r(__cosf(p1) * INV_SQRT_MF));
                *(float2*)&qps[tok * QSTR + m0 + 128] = make_float2(
                    tf32r(__sinf(p0) * INV_SQRT_MF), tf32r(__sinf(p1) * INV_SQRT_MF));
            }
        __syncthreads();

        // Step B: out[64,64] = q' @ kvT
        float oacc[2][4];
#pragma unroll
        for (int nj = 0; nj < 2; nj++)
#pragma unroll
            for (int r = 0; r < 4; r++) oacc[nj][r] = 0.f;

#pragma unroll
        for (int ks = 0; ks < 32; ks++) {
            const int kb = ks * 8;
            uint32_t af[4], bf2[2][2];
            const float* p = &qps[(tokB + g) * QSTR + kb + c];
            af[0] = __float_as_uint(p[0]);
            af[1] = __float_as_uint(p[8 * QSTR]);
            af[2] = __float_as_uint(p[4]);
            af[3] = __float_as_uint(p[8 * QSTR + 4]);
#pragma unroll
            for (int nj = 0; nj < 2; nj++) {
                const float* pb = &kvt[(dB + nj * 8 + g) * QSTR + kb + c];
                bf2[nj][0] = __float_as_uint(pb[0]);
                bf2[nj][1] = __float_as_uint(pb[4]);
            }
#pragma unroll
            for (int nj = 0; nj < 2; nj++)
                mma_tf32(oacc[nj], af, bf2[nj]);
        }

#pragma unroll
        for (int nj = 0; nj < 2; nj++) {
            int tok = l0 + tokB + g;
            int col = h * DH + dB + nj * 8 + 2 * c;
            *(float2*)(out + (size_t)(b * LL + tok) * DM + col) =
                make_float2(tf32r(oacc[nj][0]), tf32r(oacc[nj][1]));
            *(float2*)(out + (size_t)(b * LL + tok + 8) * DM + col) =
                make_float2(tf32r(oacc[nj][2]), tf32r(oacc[nj][3]));
        }
    }
}

// ---------------------------------------------------------------------------
extern "C" void kernel_launch(void* const* d_in, const int* in_sizes, int n_in,
                              void* d_out, int out_size)
{
    const float* x    = (const float*)d_in[0];
    const float* proj = (const float*)d_in[1];
    const float* Wq   = (const float*)d_in[2];
    const float* bq   = (const float*)d_in[3];
    const float* Wk   = (const float*)d_in[4];
    const float* bk   = (const float*)d_in[5];
    const float* Wv   = (const float*)d_in[6];
    const float* bv   = (const float*)d_in[7];
    const float* Wo   = (const float*)d_in[8];
    const float* bo   = (const float*)d_in[9];
    float* out = (float*)d_out;

    float *q, *k, *v, *att, *xr, *wr, *kvp, *kvf;
    cudaGetSymbolAddress((void**)&q,   g_q);
    cudaGetSymbolAddress((void**)&k,   g_k);
    cudaGetSymbolAddress((void**)&v,   g_v);
    cudaGetSymbolAddress((void**)&att, g_att);
    cudaGetSymbolAddress((void**)&xr,  g_xr);
    cudaGetSymbolAddress((void**)&wr,  g_wr);
    cudaGetSymbolAddress((void**)&kvp, g_kvp);
    cudaGetSymbolAddress((void**)&kvf, g_kv);

    static bool attr_set = false;
    if (!attr_set) {
        cudaFuncSetAttribute(qkv_gemm, cudaFuncAttributeMaxDynamicSharedMemorySize, GSMEM);
        cudaFuncSetAttribute(gemm_one, cudaFuncAttributeMaxDynamicSharedMemorySize, GSMEM);
        cudaFuncSetAttribute(feat_kv, cudaFuncAttributeMaxDynamicSharedMemorySize, FEAT_SMEM);
        cudaFuncSetAttribute(attn_mma, cudaFuncAttributeMaxDynamicSharedMemorySize, ATTN_SMEM);
        attr_set = true;
    }

    // prep: tf32-round x and all weights
    const int XN4 = TT * DM / 4;
    const int WN4 = DM * DM / 4;
    round_cp<<<XN4 / 256, 256>>>((const float4*)x, (float4*)xr, XN4);
    round_cp<<<WN4 / 256, 256>>>((const float4*)Wq, (float4*)(wr + 0 * DM * DM), WN4);
    round_cp<<<WN4 / 256, 256>>>((const float4*)Wk, (float4*)(wr + 1 * DM * DM), WN4);
    round_cp<<<WN4 / 256, 256>>>((const float4*)Wv, (float4*)(wr + 2 * DM * DM), WN4);
    round_cp<<<WN4 / 256, 256>>>((const float4*)Wo, (float4*)(wr + 3 * DM * DM), WN4);

    qkv_gemm<<<dim3(DM / 128, TT / 128, 3), 256, GSMEM>>>(xr, wr, bq, bk, bv, q, k, v);

    feat_kv<<<dim3(KV_SPLIT, HH, BB), 512, FEAT_SMEM>>>(k, v, proj, kvp);

    const int N4 = BB * HH * TWO_M * DH / 4;
    kv_reduce<<<(N4 + 255) / 256, 256>>>((const float4*)kvp, (float4*)kvf);

    attn_mma<<<dim3(LL / (64 * ACH), HH, BB), 512, ATTN_SMEM>>>(q, kvf, proj, att);

    gemm_one<<<dim3(DM / 128, TT / 128), 256, GSMEM>>>(att, wr + 3 * DM * DM, bo, out);
}

// round 5
// speedup vs baseline: 4.4602x; 1.0969x over previous
#include <cuda_runtime.h>
#include <math.h>
#include <stdint.h>

#define BB 4
#define LL 4096
#define TT (BB*LL)
#define DM 1024
#define HH 16
#define DH 64
#define MF 128
#define TWO_M 256
#define KV_SPLIT 16
#define LSPLIT (LL/KV_SPLIT)   // 256

#define INV_SQRT_DH 0.125f
#define INV_SQRT_MF 0.08838834764831843f

__device__ float g_q[TT*DM];
__device__ float g_k[TT*DM];
__device__ float g_v[TT*DM];
__device__ float g_att[TT*DM];
__device__ float g_xr[TT*DM];
__device__ float g_wr[4*DM*DM];
__device__ float g_kvp[(size_t)KV_SPLIT*BB*HH*TWO_M*DH];
__device__ float g_kv[(size_t)BB*HH*TWO_M*DH];

__device__ __forceinline__ float tf32r(float x) {
    uint32_t u;
    asm("cvt.rna.tf32.f32 %0, %1;" : "=r"(u) : "f"(x));
    return __uint_as_float(u);
}

__device__ __forceinline__ void mma_tf32(float* d, const uint32_t* a, const uint32_t* b) {
    asm volatile(
        "mma.sync.aligned.m16n8k8.row.col.f32.tf32.tf32.f32 "
        "{%0,%1,%2,%3}, {%4,%5,%6,%7}, {%8,%9}, {%0,%1,%2,%3};\n"
        : "+f"(d[0]), "+f"(d[1]), "+f"(d[2]), "+f"(d[3])
        : "r"(a[0]), "r"(a[1]), "r"(a[2]), "r"(a[3]), "r"(b[0]), "r"(b[1]));
}

__device__ __forceinline__ uint32_t smaddr(const float* p) {
    return (uint32_t)__cvta_generic_to_shared(p);
}

// ldmatrix x4: loads four 8x8 b16 tiles = one 16x8 b32 A-fragment (or two
// 8x8 b32 B-fragments). Per-lane row address supplied via offset precomputed
// by the caller (A-pattern or B-pattern).
__device__ __forceinline__ void ldsm4(uint32_t* r, uint32_t a) {
    asm volatile("ldmatrix.sync.aligned.m8n8.x4.shared.b16 {%0,%1,%2,%3}, [%4];"
                 : "=r"(r[0]), "=r"(r[1]), "=r"(r[2]), "=r"(r[3]) : "r"(a));
}

// A-pattern lane offset (within a 16-row x 8-col b32 tile), stride in floats:
//   mat = lane>>3; row = (mat&1)*8 + (lane&7); colgrp = (mat>>1)*4
#define AOFF(lane, STR) (((((lane) >> 3) & 1) * 8 + ((lane) & 7)) * (STR) + ((lane) >> 4) * 4)
// B-pattern lane offset (two consecutive 8-row n-tiles):
//   mat = lane>>3; nt_sel = mat>>1 (+8 rows); colgrp = (mat&1)*4
#define BOFF(lane, STR) ((((lane) >> 4) * 8 + ((lane) & 7)) * (STR) + (((lane) >> 3) & 1) * 4)

// ---------------------------------------------------------------------------
__global__ void round_cp(const float4* __restrict__ src, float4* __restrict__ dst, int n4)
{
    int i = blockIdx.x * 256 + threadIdx.x;
    if (i < n4) {
        float4 v = src[i];
        v.x = tf32r(v.x); v.y = tf32r(v.y); v.z = tf32r(v.z); v.w = tf32r(v.w);
        dst[i] = v;
    }
}

// ---------------------------------------------------------------------------
// GEMM body: C[128,128 tile] = A[M,1024] * W[N,1024]^T + bias
// cp.async 3-stage pipeline, ldmatrix fragment loads. 256 threads.
// ---------------------------------------------------------------------------
#define GS 3
#define GSTR 36
#define GSTAGE (128*GSTR)
#define GSMEM (2*GS*GSTAGE*4)

__device__ __forceinline__ void gemm_body(
    const float* __restrict__ A, const float* __restrict__ W,
    const float* __restrict__ bias, float* __restrict__ C)
{
    extern __shared__ float sg[];
    float* As = sg;
    float* Ws = sg + GS * GSTAGE;

    const int tid = threadIdx.x;
    const int bm = blockIdx.y * 128;
    const int bn = blockIdx.x * 128;
    const int warp = tid >> 5, lane = tid & 31;
    const int wm = (warp & 1) * 64;
    const int wn = (warp >> 1) * 32;
    const int g = lane >> 2, c = lane & 3;
    const int aoff = AOFF(lane, GSTR);
    const int boff = BOFF(lane, GSTR);

    float d[4][4][4];
#pragma unroll
    for (int mt = 0; mt < 4; mt++)
#pragma unroll
        for (int nt = 0; nt < 4; nt++)
#pragma unroll
            for (int r = 0; r < 4; r++) d[mt][nt][r] = 0.f;

    auto issue = [&](int st, int k0) {
#pragma unroll
        for (int j = 0; j < 4; j++) {
            int id = tid + j * 256;
            int row = id >> 3, kq = (id & 7) * 4;
            uint32_t da = smaddr(&As[st * GSTAGE + row * GSTR + kq]);
            uint32_t dw = smaddr(&Ws[st * GSTAGE + row * GSTR + kq]);
            asm volatile("cp.async.cg.shared.global [%0], [%1], 16;\n"
                         :: "r"(da), "l"(A + (size_t)(bm + row) * DM + k0 + kq));
            asm volatile("cp.async.cg.shared.global [%0], [%1], 16;\n"
                         :: "r"(dw), "l"(W + (size_t)(bn + row) * DM + k0 + kq));
        }
    };

    issue(0, 0);  asm volatile("cp.async.commit_group;\n");
    issue(1, 32); asm volatile("cp.async.commit_group;\n");

    const int NIT = DM / 32;
    for (int i = 0; i < NIT; i++) {
        asm volatile("cp.async.wait_group 1;\n");
        __syncthreads();
        if (i + 2 < NIT) issue((i + 2) % GS, (i + 2) * 32);
        asm volatile("cp.async.commit_group;\n");

        const float* Ab = As + (i % GS) * GSTAGE;
        const float* Wb = Ws + (i % GS) * GSTAGE;
#pragma unroll
        for (int ks = 0; ks < 4; ks++) {
            const int kb = ks * 8;
            uint32_t a[4][4], bq2[2][4];
#pragma unroll
            for (int mt = 0; mt < 4; mt++)
                ldsm4(a[mt], smaddr(Ab + (wm + mt * 16) * GSTR + kb + aoff));
            ldsm4(bq2[0], smaddr(Wb + wn * GSTR + kb + boff));
            ldsm4(bq2[1], smaddr(Wb + (wn + 16) * GSTR + kb + boff));
#pragma unroll
            for (int mt = 0; mt < 4; mt++)
#pragma unroll
                for (int nt = 0; nt < 4; nt++)
                    mma_tf32(d[mt][nt], a[mt], &bq2[nt >> 1][(nt & 1) * 2]);
        }
    }

#pragma unroll
    for (int nt = 0; nt < 4; nt++) {
        int col = bn + wn + nt * 8 + 2 * c;
        float b0 = bias[col], b1 = bias[col + 1];
#pragma unroll
        for (int mt = 0; mt < 4; mt++) {
            int row = bm + wm + mt * 16 + g;
            *(float2*)(C + (size_t)row * DM + col) =
                make_float2(d[mt][nt][0] + b0, d[mt][nt][1] + b1);
            *(float2*)(C + (size_t)(row + 8) * DM + col) =
                make_float2(d[mt][nt][2] + b0, d[mt][nt][3] + b1);
        }
    }
}

__global__ __launch_bounds__(256, 2) void qkv_gemm(
    const float* __restrict__ A, const float* __restrict__ Wr,
    const float* __restrict__ bq, const float* __restrict__ bk, const float* __restrict__ bv,
    float* __restrict__ q, float* __restrict__ k, float* __restrict__ v)
{
    int z = blockIdx.z;
    const float* W = Wr + (size_t)z * DM * DM;
    const float* bias = (z == 0) ? bq : (z == 1) ? bk : bv;
    float* C = (z == 0) ? q : (z == 1) ? k : v;
    gemm_body(A, W, bias, C);
}

__global__ __launch_bounds__(256, 2) void gemm_one(
    const float* __restrict__ A, const float* __restrict__ W,
    const float* __restrict__ bias, float* __restrict__ C)
{
    gemm_body(A, W, bias, C);
}

// ---------------------------------------------------------------------------
// feat_kv: per (split,h,b): kv[256,64] = sum_l k'(l)^T v(l). 512 threads.
// ---------------------------------------------------------------------------
#define FSTR 68
#define FEAT_SMEM ((128*FSTR + 3*64*FSTR + 256*FSTR) * 4)

__global__ __launch_bounds__(512) void feat_kv(
    const float* __restrict__ Kmat, const float* __restrict__ Vmat,
    const float* __restrict__ proj, float* __restrict__ kvp)
{
    extern __shared__ float sm[];
    float* projT = sm;                    // [128][68]
    float* ksh   = projT + 128 * FSTR;    // [64][68]
    float* ksl   = ksh   + 64 * FSTR;     // [64][68]
    float* vts   = ksl   + 64 * FSTR;     // [64 d][68 tok]
    float* kpt   = vts   + 64 * FSTR;     // [256 m'][68 tok]

    const int split = blockIdx.x, h = blockIdx.y, b = blockIdx.z;
    const int tid = threadIdx.x;
    const int warp = tid >> 5, lane = tid & 31;
    const int g = lane >> 2, c = lane & 3;
    const int aoff = AOFF(lane, FSTR);
    const int boff = BOFF(lane, FSTR);

    for (int it = tid; it < 2048; it += 512) {
        int d = it >> 5;
        int m4 = (it & 31) * 4;
        float4 pv = *(const float4*)(proj + d * MF + m4);
        projT[(m4 + 0) * FSTR + d] = tf32r(pv.x);
        projT[(m4 + 1) * FSTR + d] = tf32r(pv.y);
        projT[(m4 + 2) * FSTR + d] = tf32r(pv.z);
        projT[(m4 + 3) * FSTR + d] = tf32r(pv.w);
    }

    float kvacc[4][2][4];
#pragma unroll
    for (int mi = 0; mi < 4; mi++)
#pragma unroll
        for (int nj = 0; nj < 2; nj++)
#pragma unroll
            for (int r = 0; r < 4; r++) kvacc[mi][nj][r] = 0.f;

    const int wtokA = (warp & 3) * 16, wmA = (warp >> 2) * 32;
    const int mB0 = (warp & 3) * 64, dB0 = (warp >> 2) * 16;
    const int l0 = split * LSPLIT;

    for (int ch = 0; ch < LSPLIT; ch += 64) {
        __syncthreads();
        for (int it = tid; it < 1024; it += 512) {
            int t = it >> 4;
            int d4 = (it & 15) * 4;
            size_t row = (size_t)(b * LL + l0 + ch + t) * DM + h * DH + d4;
            float4 kvv = *(const float4*)(Kmat + row);
            float hx = tf32r(kvv.x), hy = tf32r(kvv.y), hz = tf32r(kvv.z), hw = tf32r(kvv.w);
            *(float4*)&ksh[t * FSTR + d4] = make_float4(hx, hy, hz, hw);
            *(float4*)&ksl[t * FSTR + d4] = make_float4(
                tf32r(kvv.x - hx), tf32r(kvv.y - hy), tf32r(kvv.z - hz), tf32r(kvv.w - hw));
            float4 vv = *(const float4*)(Vmat + row);
            vts[(d4 + 0) * FSTR + t] = tf32r(vv.x);
            vts[(d4 + 1) * FSTR + t] = tf32r(vv.y);
            vts[(d4 + 2) * FSTR + t] = tf32r(vv.z);
            vts[(d4 + 3) * FSTR + t] = tf32r(vv.w);
        }
        __syncthreads();

        // Step A: P[64,128] = K @ projT (hi/lo)
        float pacc[4][4];
#pragma unroll
        for (int nj = 0; nj < 4; nj++)
#pragma unroll
            for (int r = 0; r < 4; r++) pacc[nj][r] = 0.f;

#pragma unroll
        for (int ks = 0; ks < 8; ks++) {
            const int kb = ks * 8;
            uint32_t ah[4], al[4], bfr[2][4];
            ldsm4(ah, smaddr(ksh + wtokA * FSTR + kb + aoff));
            ldsm4(al, smaddr(ksl + wtokA * FSTR + kb + aoff));
            ldsm4(bfr[0], smaddr(projT + wmA * FSTR + kb + boff));
            ldsm4(bfr[1], smaddr(projT + (wmA + 16) * FSTR + kb + boff));
#pragma unroll
            for (int nj = 0; nj < 4; nj++) {
                mma_tf32(pacc[nj], ah, &bfr[nj >> 1][(nj & 1) * 2]);
                mma_tf32(pacc[nj], al, &bfr[nj >> 1][(nj & 1) * 2]);
            }
        }

#pragma unroll
        for (int nj = 0; nj < 4; nj++)
#pragma unroll
            for (int r = 0; r < 4; r++) {
                int tok = wtokA + g + (r >> 1) * 8;
                int m = wmA + nj * 8 + 2 * c + (r & 1);
                float p = pacc[nj][r] * INV_SQRT_DH;
                kpt[m * FSTR + tok] = tf32r(__cosf(p) * INV_SQRT_MF);
                kpt[(m + 128) * FSTR + tok] = tf32r(__sinf(p) * INV_SQRT_MF);
            }
        __syncthreads();

        // Step B: kv[256,64] += k'T @ V
#pragma unroll
        for (int ks = 0; ks < 8; ks++) {
            const int kb = ks * 8;
            uint32_t af[4][4], bv2[4];
#pragma unroll
            for (int mi = 0; mi < 4; mi++)
                ldsm4(af[mi], smaddr(kpt + (mB0 + mi * 16) * FSTR + kb + aoff));
            ldsm4(bv2, smaddr(vts + dB0 * FSTR + kb + boff));
#pragma unroll
            for (int mi = 0; mi < 4; mi++)
#pragma unroll
                for (int nj = 0; nj < 2; nj++)
                    mma_tf32(kvacc[mi][nj], af[mi], &bv2[nj * 2]);
        }
    }

    float* outp = kvp + ((size_t)split * BB * HH + b * HH + h) * TWO_M * DH;
#pragma unroll
    for (int mi = 0; mi < 4; mi++)
#pragma unroll
        for (int nj = 0; nj < 2; nj++) {
            int m = mB0 + mi * 16 + g;
            int d = dB0 + nj * 8 + 2 * c;
            *(float2*)(outp + m * DH + d) =
                make_float2(kvacc[mi][nj][0], kvacc[mi][nj][1]);
            *(float2*)(outp + (m + 8) * DH + d) =
                make_float2(kvacc[mi][nj][2], kvacc[mi][nj][3]);
        }
}

// ---------------------------------------------------------------------------
__global__ void kv_reduce(const float4* __restrict__ kvp, float4* __restrict__ kv)
{
    const int N4 = BB * HH * TWO_M * DH / 4;
    int i = blockIdx.x * blockDim.x + threadIdx.x;
    if (i >= N4) return;
    float4 s = kvp[i];
#pragma unroll
    for (int sp = 1; sp < KV_SPLIT; sp++) {
        float4 t = kvp[(size_t)sp * N4 + i];
        s.x += t.x; s.y += t.y; s.z += t.z; s.w += t.w;
    }
    kv[i] = s;
}

// ---------------------------------------------------------------------------
// attn: out[tok,64] = q'[tok,256] @ kv[256,64]. 512 threads, ACH chunks/block.
// ---------------------------------------------------------------------------
#define ACH 4
#define QSTR 260
#define ATTN_SMEM ((128*FSTR + 2*64*FSTR + 2*64*QSTR) * 4)

__global__ __launch_bounds__(512) void attn_mma(
    const float* __restrict__ Q, const float* __restrict__ kv,
    const float* __restrict__ proj, float* __restrict__ out)
{
    extern __shared__ float sm[];
    float* projT = sm;                    // [128][68]
    float* qsh   = projT + 128 * FSTR;    // [64][68]
    float* qsl   = qsh   + 64 * FSTR;     // [64][68]
    float* qps   = qsl   + 64 * FSTR;     // [64 tok][260]
    float* kvt   = qps   + 64 * QSTR;     // [64 d][260 m']

    const int h = blockIdx.y, b = blockIdx.z;
    const int tid = threadIdx.x;
    const int warp = tid >> 5, lane = tid & 31;
    const int g = lane >> 2, c = lane & 3;
    const int aoffF = AOFF(lane, FSTR);
    const int boffF = BOFF(lane, FSTR);
    const int aoffQ = AOFF(lane, QSTR);
    const int boffQ = BOFF(lane, QSTR);

    for (int it = tid; it < 2048; it += 512) {
        int d = it >> 5;
        int m4 = (it & 31) * 4;
        float4 pv = *(const float4*)(proj + d * MF + m4);
        projT[(m4 + 0) * FSTR + d] = tf32r(pv.x);
        projT[(m4 + 1) * FSTR + d] = tf32r(pv.y);
        projT[(m4 + 2) * FSTR + d] = tf32r(pv.z);
        projT[(m4 + 3) * FSTR + d] = tf32r(pv.w);
    }
    const float* kvsrc = kv + ((size_t)(b * HH + h)) * TWO_M * DH;
    for (int it = tid; it < 4096; it += 512) {
        int m = it >> 4;
        int d4 = (it & 15) * 4;
        float4 v = *(const float4*)(kvsrc + m * DH + d4);
        kvt[(d4 + 0) * QSTR + m] = tf32r(v.x);
        kvt[(d4 + 1) * QSTR + m] = tf32r(v.y);
        kvt[(d4 + 2) * QSTR + m] = tf32r(v.z);
        kvt[(d4 + 3) * QSTR + m] = tf32r(v.w);
    }

    const int wtokA = (warp & 3) * 16, wmA = (warp >> 2) * 32;
    const int tokB = (warp & 3) * 16, dB = (warp >> 2) * 16;

    for (int cc = 0; cc < ACH; cc++) {
        const int l0 = (blockIdx.x * ACH + cc) * 64;
        __syncthreads();
        for (int it = tid; it < 1024; it += 512) {
            int t = it >> 4;
            int d4 = (it & 15) * 4;
            size_t row = (size_t)(b * LL + l0 + t) * DM + h * DH + d4;
            float4 qv = *(const float4*)(Q + row);
            float hx = tf32r(qv.x), hy = tf32r(qv.y), hz = tf32r(qv.z), hw = tf32r(qv.w);
            *(float4*)&qsh[t * FSTR + d4] = make_float4(hx, hy, hz, hw);
            *(float4*)&qsl[t * FSTR + d4] = make_float4(
                tf32r(qv.x - hx), tf32r(qv.y - hy), tf32r(qv.z - hz), tf32r(qv.w - hw));
        }
        __syncthreads();

        // Step A: P = Q @ projT (hi/lo)
        float pacc[4][4];
#pragma unroll
        for (int nj = 0; nj < 4; nj++)
#pragma unroll
            for (int r = 0; r < 4; r++) pacc[nj][r] = 0.f;

#pragma unroll
        for (int ks = 0; ks < 8; ks++) {
            const int kb = ks * 8;
            uint32_t ah[4], al[4], bfr[2][4];
            ldsm4(ah, smaddr(qsh + wtokA * FSTR + kb + aoffF));
            ldsm4(al, smaddr(qsl + wtokA * FSTR + kb + aoffF));
            ldsm4(bfr[0], smaddr(projT + wmA * FSTR + kb + boffF));
            ldsm4(bfr[1], smaddr(projT + (wmA + 16) * FSTR + kb + boffF));
#pragma unroll
            for (int nj = 0; nj < 4; nj++) {
                mma_tf32(pacc[nj], ah, &bfr[nj >> 1][(nj & 1) * 2]);
                mma_tf32(pacc[nj], al, &bfr[nj >> 1][(nj & 1) * 2]);
            }
        }

#pragma unroll
        for (int nj = 0; nj < 4; nj++)
#pragma unroll
            for (int half = 0; half < 2; half++) {
                int tok = wtokA + g + half * 8;
                int m0 = wmA + nj * 8 + 2 * c;
                float p0 = pacc[nj][half * 2 + 0] * INV_SQRT_DH;
                float p1 = pacc[nj][half * 2 + 1] * INV_SQRT_DH;
                *(float2*)&qps[tok * QSTR + m0] = make_float2(
                    tf32r(__cosf(p0) * INV_SQRT_MF), tf32r(__cosf(p1) * INV_SQRT_MF));
                *(float2*)&qps[tok * QSTR + m0 + 128] = make_float2(
                    tf32r(__sinf(p0) * INV_SQRT_MF), tf32r(__sinf(p1) * INV_SQRT_MF));
            }
        __syncthreads();

        // Step B: out[64,64] = q' @ kvT
        float oacc[2][4];
#pragma unroll
        for (int nj = 0; nj < 2; nj++)
#pragma unroll
            for (int r = 0; r < 4; r++) oacc[nj][r] = 0.f;

#pragma unroll
        for (int ks = 0; ks < 32; ks++) {
            const int kb = ks * 8;
            uint32_t af[4], bv2[4];
            ldsm4(af, smaddr(qps + tokB * QSTR + kb + aoffQ));
            ldsm4(bv2, smaddr(kvt + dB * QSTR + kb + boffQ));
#pragma unroll
            for (int nj = 0; nj < 2; nj++)
                mma_tf32(oacc[nj], af, &bv2[nj * 2]);
        }

#pragma unroll
        for (int nj = 0; nj < 2; nj++) {
            int tok = l0 + tokB + g;
            int col = h * DH + dB + nj * 8 + 2 * c;
            *(float2*)(out + (size_t)(b * LL + tok) * DM + col) =
                make_float2(tf32r(oacc[nj][0]), tf32r(oacc[nj][1]));
            *(float2*)(out + (size_t)(b * LL + tok + 8) * DM + col) =
                make_float2(tf32r(oacc[nj][2]), tf32r(oacc[nj][3]));
        }
    }
}

// ---------------------------------------------------------------------------
extern "C" void kernel_launch(void* const* d_in, const int* in_sizes, int n_in,
                              void* d_out, int out_size)
{
    const float* x    = (const float*)d_in[0];
    const float* proj = (const float*)d_in[1];
    const float* Wq   = (const float*)d_in[2];
    const float* bq   = (const float*)d_in[3];
    const float* Wk   = (const float*)d_in[4];
    const float* bk   = (const float*)d_in[5];
    const float* Wv   = (const float*)d_in[6];
    const float* bv   = (const float*)d_in[7];
    const float* Wo   = (const float*)d_in[8];
    const float* bo   = (const float*)d_in[9];
    float* out = (float*)d_out;

    float *q, *k, *v, *att, *xr, *wr, *kvp, *kvf;
    cudaGetSymbolAddress((void**)&q,   g_q);
    cudaGetSymbolAddress((void**)&k,   g_k);
    cudaGetSymbolAddress((void**)&v,   g_v);
    cudaGetSymbolAddress((void**)&att, g_att);
    cudaGetSymbolAddress((void**)&xr,  g_xr);
    cudaGetSymbolAddress((void**)&wr,  g_wr);
    cudaGetSymbolAddress((void**)&kvp, g_kvp);
    cudaGetSymbolAddress((void**)&kvf, g_kv);

    static bool attr_set = false;
    if (!attr_set) {
        cudaFuncSetAttribute(qkv_gemm, cudaFuncAttributeMaxDynamicSharedMemorySize, GSMEM);
        cudaFuncSetAttribute(gemm_one, cudaFuncAttributeMaxDynamicSharedMemorySize, GSMEM);
        cudaFuncSetAttribute(feat_kv, cudaFuncAttributeMaxDynamicSharedMemorySize, FEAT_SMEM);
        cudaFuncSetAttribute(attn_mma, cudaFuncAttributeMaxDynamicSharedMemorySize, ATTN_SMEM);
        attr_set = true;
    }

    const int XN4 = TT * DM / 4;
    const int WN4 = DM * DM / 4;
    round_cp<<<XN4 / 256, 256>>>((const float4*)x, (float4*)xr, XN4);
    round_cp<<<WN4 / 256, 256>>>((const float4*)Wq, (float4*)(wr + 0 * DM * DM), WN4);
    round_cp<<<WN4 / 256, 256>>>((const float4*)Wk, (float4*)(wr + 1 * DM * DM), WN4);
    round_cp<<<WN4 / 256, 256>>>((const float4*)Wv, (float4*)(wr + 2 * DM * DM), WN4);
    round_cp<<<WN4 / 256, 256>>>((const float4*)Wo, (float4*)(wr + 3 * DM * DM), WN4);

    qkv_gemm<<<dim3(DM / 128, TT / 128, 3), 256, GSMEM>>>(xr, wr, bq, bk, bv, q, k, v);

    feat_kv<<<dim3(KV_SPLIT, HH, BB), 512, FEAT_SMEM>>>(k, v, proj, kvp);

    const int N4 = BB * HH * TWO_M * DH / 4;
    kv_reduce<<<(N4 + 255) / 256, 256>>>((const float4*)kvp, (float4*)kvf);

    attn_mma<<<dim3(LL / (64 * ACH), HH, BB), 512, ATTN_SMEM>>>(q, kvf, proj, att);

    gemm_one<<<dim3(DM / 128, TT / 128), 256, GSMEM>>>(att, wr + 3 * DM * DM, bo, out);
}